// round 4
// baseline (speedup 1.0000x reference)
#include <cuda_runtime.h>
#include <math.h>

#define SQn   2048
#define SKn   64
#define Cn    256
#define HWn   256
#define En    512
#define NPn   (SQn*SKn)      /* 131072 points */
#define NHn   8
#define HDn   64

// ---------------- scratch (static device allocations) ----------------
__device__ float g_Zt[(size_t)Cn*HWn*HWn];     // 67 MB   Zt[x][y][c]
__device__ float g_key[(size_t)NPn*En];        // 268 MB  key (131072 x 512)
__device__ float g_query[(size_t)SQn*En];      // 4 MB
__device__ float g_ql[(size_t)SQn*En];         // 4 MB
__device__ float g_qk[(size_t)SQn*NHn*En];     // 33.5 MB qk[b][h][j]
__device__ float g_ctx[(size_t)SQn*NHn*En];    // 33.5 MB ctx[b][h][j]
__device__ float g_out1[(size_t)SQn*En];       // 4 MB

// ---------------- 1) transpose Z (C, HW*HW) -> Zt (HW*HW, C) ----------------
__global__ void transpose_kernel(const float* __restrict__ Z) {
    __shared__ float tile[32][33];
    int xy0 = blockIdx.x * 32;
    int c0  = blockIdx.y * 32;
    int tx = threadIdx.x, ty = threadIdx.y;   // 32 x 8
    #pragma unroll
    for (int i = 0; i < 32; i += 8)
        tile[ty + i][tx] = Z[(long)(c0 + ty + i) * (HWn*HWn) + xy0 + tx];
    __syncthreads();
    #pragma unroll
    for (int i = 0; i < 32; i += 8)
        g_Zt[(long)(xy0 + ty + i) * Cn + c0 + tx] = tile[tx][ty + i];
}

// ---------------- 2) bilinear interp -> key cols [0,256) ----------------
// Reference does interp(C,N).reshape(-1,C): flat reinterpretation. Writing
// bilin(c,p) to key[c*512 + p/256][p%256] reproduces it exactly.
__global__ void interp_kernel(const float* __restrict__ r) {
    int p  = blockIdx.x * 256 + threadIdx.x;   // point, block p-range aligned to 256
    int c0 = blockIdx.y * 32;                  // channel group
    float x = r[2*p], y = r[2*p + 1];
    int x1 = (int)x, y1 = (int)y;
    float dx = x - (float)x1, dy = y - (float)y1;
    const float* z11 = g_Zt + ((long)x1 * HWn + y1) * Cn + c0;
    const float* z12 = z11 + Cn;            // (x1, y1+1)
    const float* z21 = z11 + (long)HWn*Cn;  // (x1+1, y1)
    const float* z22 = z21 + Cn;            // (x1+1, y1+1)
    long base0 = ((long)c0 * 512 + (p >> 8)) * 512 + (p & 255);
    float omdx = 1.0f - dx, omdy = 1.0f - dy;
    #pragma unroll
    for (int cc = 0; cc < 32; cc += 4) {
        float4 a = *(const float4*)(z11 + cc);
        float4 b = *(const float4*)(z21 + cc);
        float4 c = *(const float4*)(z12 + cc);
        float4 d = *(const float4*)(z22 + cc);
        float v0, v1, v2, v3;
        { float R1 = a.x*omdx + b.x*dx, R2 = c.x*omdx + d.x*dx; v0 = R1*omdy + R2*dy; }
        { float R1 = a.y*omdx + b.y*dx, R2 = c.y*omdx + d.y*dx; v1 = R1*omdy + R2*dy; }
        { float R1 = a.z*omdx + b.z*dx, R2 = c.z*omdx + d.z*dx; v2 = R1*omdy + R2*dy; }
        { float R1 = a.w*omdx + b.w*dx, R2 = c.w*omdx + d.w*dx; v3 = R1*omdy + R2*dy; }
        g_key[base0 + (long)(cc + 0) * (512*512)] = v0;
        g_key[base0 + (long)(cc + 1) * (512*512)] = v1;
        g_key[base0 + (long)(cc + 2) * (512*512)] = v2;
        g_key[base0 + (long)(cc + 3) * (512*512)] = v3;
    }
}

// ---------------- 3) r_proj -> key cols [256,512) ----------------
__global__ void rproj_kernel(const float* __restrict__ r,
                             const float* __restrict__ w1,
                             const float* __restrict__ b1) {
    int i = blockIdx.x;          // point 0..131071
    int h = threadIdx.x;         // 0..255
    float x = r[2*i], y = r[2*i + 1];
    g_key[(long)i * En + 256 + h] = x * w1[2*h] + y * w1[2*h + 1] + b1[h];
}

// ---------------- 4) build query = [q_z | Q@w2^T + b2]; also write q_z to out ----------------
__global__ void query_kernel(const float* __restrict__ Q,
                             const float* __restrict__ q_z,
                             const float* __restrict__ w2,
                             const float* __restrict__ b2,
                             float* __restrict__ outp) {
    int b = blockIdx.x, t = threadIdx.x;   // 512 threads
    if (t < 256) {
        float v = q_z[(long)b * 256 + t];
        g_query[(long)b * En + t] = v;
        outp[(long)b * 768 + t] = v;       // concat([q_z, out]) left half
    } else {
        int h = t - 256;
        float v = Q[b*3+0]*w2[h*3+0] + Q[b*3+1]*w2[h*3+1] + Q[b*3+2]*w2[h*3+2] + b2[h];
        g_query[(long)b * En + t] = v;
    }
}

// ---------------- generic batched GEMM: C[m][n] = sum_k A[m*lda+k] * B[n*ldbn + k*ldbk] + bias[n] ----------------
// 64x64 tile, KC=16, 256 threads, 4x4 micro-tile. All M,N div by 64; K div by 16.
__global__ __launch_bounds__(256)
void gemm_kernel(const float* __restrict__ A, int lda, long sA,
                 const float* __restrict__ B, int ldbn, int ldbk, long sB,
                 float* __restrict__ Cp, int ldc, long sC,
                 const float* __restrict__ bias, long sBias,
                 int M, int N, int K) {
    int batch = blockIdx.z;
    A += (long)batch * sA;
    B += (long)batch * sB;
    Cp += (long)batch * sC;
    if (bias) bias += (long)batch * sBias;

    __shared__ float As[64][17];
    __shared__ float Bs[64][17];
    int tid = threadIdx.x;
    int tx = tid & 15, ty = tid >> 4;
    int m0 = blockIdx.y * 64, n0 = blockIdx.x * 64;
    float acc[4][4] = {};

    for (int k0 = 0; k0 < K; k0 += 16) {
        {   // load A tile 64x16 via float4
            int rr = tid >> 2, c4 = (tid & 3) * 4;
            float4 v = *(const float4*)(&A[(long)(m0 + rr) * lda + k0 + c4]);
            As[rr][c4] = v.x; As[rr][c4+1] = v.y; As[rr][c4+2] = v.z; As[rr][c4+3] = v.w;
        }
        if (ldbk == 1) { // B row-major over n, k contiguous
            int rr = tid >> 2, c4 = (tid & 3) * 4;
            float4 v = *(const float4*)(&B[(long)(n0 + rr) * ldbn + k0 + c4]);
            Bs[rr][c4] = v.x; Bs[rr][c4+1] = v.y; Bs[rr][c4+2] = v.z; Bs[rr][c4+3] = v.w;
        } else {         // n contiguous (ldbn==1), k strided
            #pragma unroll
            for (int q = 0; q < 4; q++) {
                int idx = tid + 256 * q;
                int nn = idx & 63, kk = idx >> 6;
                Bs[nn][kk] = B[(long)(n0 + nn) * ldbn + (long)(k0 + kk) * ldbk];
            }
        }
        __syncthreads();
        #pragma unroll
        for (int k = 0; k < 16; k++) {
            float a[4], b[4];
            #pragma unroll
            for (int i = 0; i < 4; i++) a[i] = As[ty*4 + i][k];
            #pragma unroll
            for (int j = 0; j < 4; j++) b[j] = Bs[tx*4 + j][k];
            #pragma unroll
            for (int i = 0; i < 4; i++)
                #pragma unroll
                for (int j = 0; j < 4; j++)
                    acc[i][j] += a[i] * b[j];
        }
        __syncthreads();
    }
    #pragma unroll
    for (int i = 0; i < 4; i++) {
        int m = m0 + ty*4 + i;
        #pragma unroll
        for (int j = 0; j < 4; j++) {
            int n = n0 + tx*4 + j;
            float v = acc[i][j];
            if (bias) v += bias[n];
            Cp[(long)m * ldc + n] = v;
        }
    }
}

// ---------------- 5) fused attention per query: scores -> softmax -> ctx ----------------
// scores[h][k] = (1/8) * qk[b][h][:] . key[b*64+k][:]   (bias term constant over k -> cancels)
// ctx[b][h][j] = sum_k attn[h][k] * key[b*64+k][j]
__global__ __launch_bounds__(512)
void attn_kernel(const float* __restrict__ qk, const float* __restrict__ key,
                 float* __restrict__ ctx) {
    __shared__ float4 qks4[1024];          // 8*512 floats
    __shared__ float skey[64][65];
    __shared__ float sc[8][64];
    __shared__ float sm[8], srs[8];

    int b = blockIdx.x;
    int t = threadIdx.x;
    int h = t >> 6, k = t & 63;
    float* qks = (float*)qks4;

    // load qk[b] (16 KB)
    {
        const float4* src = (const float4*)(qk + (long)b * (NHn*En));
        for (int i = t; i < 1024; i += 512) qks4[i] = src[i];
    }

    const float* keyb = key + (long)b * SKn * En;
    int lrow = t >> 3, lc8 = (t & 7) * 8;

    // ---- phase 1: scores ----
    float acc = 0.0f;
    for (int j0 = 0; j0 < En; j0 += 64) {
        __syncthreads();
        const float* srcK = keyb + (long)lrow * En + j0 + lc8;
        float4 v0 = *(const float4*)srcK;
        float4 v1 = *(const float4*)(srcK + 4);
        skey[lrow][lc8+0] = v0.x; skey[lrow][lc8+1] = v0.y;
        skey[lrow][lc8+2] = v0.z; skey[lrow][lc8+3] = v0.w;
        skey[lrow][lc8+4] = v1.x; skey[lrow][lc8+5] = v1.y;
        skey[lrow][lc8+6] = v1.z; skey[lrow][lc8+7] = v1.w;
        __syncthreads();
        const float* qrow = qks + h * En + j0;
        #pragma unroll
        for (int jj = 0; jj < 64; jj++)
            acc += qrow[jj] * skey[k][jj];
    }
    float score = acc * 0.125f;   // / sqrt(64)
    __syncthreads();
    sc[h][k] = score;
    __syncthreads();

    // ---- softmax over k (64) per head ----
    if (t < 8) {
        float mx = -1e30f;
        #pragma unroll 8
        for (int i = 0; i < 64; i++) mx = fmaxf(mx, sc[t][i]);
        float s = 0.0f;
        #pragma unroll 8
        for (int i = 0; i < 64; i++) s += expf(sc[t][i] - mx);
        sm[t] = mx; srs[t] = 1.0f / s;
    }
    __syncthreads();
    float attn = expf(score - sm[h]) * srs[h];
    sc[h][k] = attn;   // reuse as attn storage

    // ---- phase 3: ctx = attn @ key ----
    float* ctxb = ctx + (long)b * (NHn*En);
    for (int j0 = 0; j0 < En; j0 += 64) {
        __syncthreads();
        const float* srcK = keyb + (long)lrow * En + j0 + lc8;
        float4 v0 = *(const float4*)srcK;
        float4 v1 = *(const float4*)(srcK + 4);
        skey[lrow][lc8+0] = v0.x; skey[lrow][lc8+1] = v0.y;
        skey[lrow][lc8+2] = v0.z; skey[lrow][lc8+3] = v0.w;
        skey[lrow][lc8+4] = v1.x; skey[lrow][lc8+5] = v1.y;
        skey[lrow][lc8+6] = v1.z; skey[lrow][lc8+7] = v1.w;
        __syncthreads();
        float a2 = 0.0f;
        #pragma unroll
        for (int kk = 0; kk < 64; kk++)
            a2 += sc[h][kk] * skey[kk][k];
        ctxb[h * En + j0 + k] = a2;
    }
}

// ---------------- host launcher ----------------
extern "C" void kernel_launch(void* const* d_in, const int* in_sizes, int n_in,
                              void* d_out, int out_size) {
    const float* Z          = (const float*)d_in[0];
    const float* Q          = (const float*)d_in[1];
    const float* q_z        = (const float*)d_in[2];
    const float* r          = (const float*)d_in[3];
    const float* w1         = (const float*)d_in[4];
    const float* b1         = (const float*)d_in[5];
    const float* w2         = (const float*)d_in[6];
    const float* b2         = (const float*)d_in[7];
    const float* in_proj_w  = (const float*)d_in[8];
    const float* in_proj_b  = (const float*)d_in[9];
    const float* out_proj_w = (const float*)d_in[10];
    const float* out_proj_b = (const float*)d_in[11];
    float* outp = (float*)d_out;

    float *pZt, *pKey, *pQuery, *pQl, *pQk, *pCtx, *pOut1;
    cudaGetSymbolAddress((void**)&pZt,    g_Zt);
    cudaGetSymbolAddress((void**)&pKey,   g_key);
    cudaGetSymbolAddress((void**)&pQuery, g_query);
    cudaGetSymbolAddress((void**)&pQl,    g_ql);
    cudaGetSymbolAddress((void**)&pQk,    g_qk);
    cudaGetSymbolAddress((void**)&pCtx,   g_ctx);
    cudaGetSymbolAddress((void**)&pOut1,  g_out1);

    // 1) transpose Z -> Zt
    transpose_kernel<<<dim3((HWn*HWn)/32, Cn/32), dim3(32, 8)>>>(Z);

    // 2) bilinear interp -> key[:, :256]
    interp_kernel<<<dim3(NPn/256, Cn/32), 256>>>(r);

    // 3) r_proj -> key[:, 256:]
    rproj_kernel<<<NPn, 256>>>(r, w1, b1);

    // 4) query = [q_z | Q@w2^T + b2]; also write q_z half of output
    query_kernel<<<SQn, 512>>>(Q, q_z, w2, b2, outp);

    // 5) ql = query @ Wq^T + bq   (Wq = in_proj_w rows [0,512))
    gemm_kernel<<<dim3(En/64, SQn/64, 1), 256>>>(
        pQuery, En, 0L,
        in_proj_w, En, 1, 0L,
        pQl, En, 0L,
        in_proj_b, 0L,
        SQn, En, En);

    // 6) qk[b][h][:] = sum_d ql[b][h*64+d] * Wk[h*64+d][:]   (Wk = rows [512,1024))
    //    per-head batched: B[n][k] = in_proj_w[(512 + h*64 + k)*512 + n]
    gemm_kernel<<<dim3(En/64, SQn/64, NHn), 256>>>(
        pQl, En, (long)HDn,
        in_proj_w + (long)En*En, 1, En, (long)HDn*En,
        pQk, NHn*En, (long)En,
        (const float*)0, 0L,
        SQn, En, HDn);

    // 7) fused attention: scores -> softmax -> ctx
    attn_kernel<<<SQn, 512>>>(pQk, pKey, pCtx);

    // 8) out1[b][h*64+d] = ctx[b][h][:] . Wv[h*64+d][:] + bv   (Wv = rows [1024,1536))
    gemm_kernel<<<dim3(HDn/64, SQn/64, NHn), 256>>>(
        pCtx, NHn*En, (long)En,
        in_proj_w + (long)2*En*En, En, 1, (long)HDn*En,
        pOut1, En, (long)HDn,
        in_proj_b + (long)2*En, (long)HDn,
        SQn, HDn, En);

    // 9) fin = out1 @ Wo^T + bo, written into d_out columns [256,768)
    gemm_kernel<<<dim3(En/64, SQn/64, 1), 256>>>(
        pOut1, En, 0L,
        out_proj_w, En, 1, 0L,
        outp + 256, 768, 0L,
        out_proj_b, 0L,
        SQn, En, En);
}

// round 5
// speedup vs baseline: 1.4259x; 1.4259x over previous
#include <cuda_runtime.h>
#include <math.h>

#define SQn   2048
#define SKn   64
#define Cn    256
#define HWn   256
#define En    512
#define NPn   (SQn*SKn)
#define NHn   8
#define HDn   64

// ---------------- scratch ----------------
__device__ float g_Zt[(size_t)Cn*HWn*HWn];      // 67 MB   Zt[x][y][c]
__device__ float g_key2[(size_t)NPn*256];       // 134 MB  interp half of key (131072 x 256)
__device__ float g_query[(size_t)SQn*En];
__device__ float g_ql[(size_t)SQn*En];
__device__ float g_qk[(size_t)SQn*NHn*En];      // qk[b][h][j]
__device__ float g_ctx[(size_t)SQn*NHn*En];     // ctx[b][h][j]
__device__ float g_out1[(size_t)SQn*En];

// ---------------- 1) transpose Z (C, HW*HW) -> Zt (HW*HW, C) ----------------
__global__ void transpose_kernel(const float* __restrict__ Z) {
    __shared__ float tile[32][33];
    int xy0 = blockIdx.x * 32;
    int c0  = blockIdx.y * 32;
    int tx = threadIdx.x, ty = threadIdx.y;   // 32 x 8
    #pragma unroll
    for (int i = 0; i < 32; i += 8)
        tile[ty + i][tx] = Z[(long)(c0 + ty + i) * (HWn*HWn) + xy0 + tx];
    __syncthreads();
    #pragma unroll
    for (int i = 0; i < 32; i += 8)
        g_Zt[(long)(xy0 + ty + i) * Cn + c0 + tx] = tile[tx][ty + i];
}

// ---------------- 2) bilinear interp -> key2 (131072 x 256, scrambled rows) ----------------
// reference reshape(-1,C) is a flat reinterpretation: bilin(c,p) lands at
// key row (c*512 + p/256), col (p%256). key2 holds cols [0,256) of key.
__global__ void interp_kernel(const float* __restrict__ r) {
    int p  = blockIdx.x * 256 + threadIdx.x;
    int c0 = blockIdx.y * 32;
    float x = r[2*p], y = r[2*p + 1];
    int x1 = (int)x, y1 = (int)y;
    float dx = x - (float)x1, dy = y - (float)y1;
    const float* z11 = g_Zt + ((long)x1 * HWn + y1) * Cn + c0;
    const float* z12 = z11 + Cn;
    const float* z21 = z11 + (long)HWn*Cn;
    const float* z22 = z21 + Cn;
    long base0 = ((long)c0 * 512 + (p >> 8)) * 256 + (p & 255);
    float omdx = 1.0f - dx, omdy = 1.0f - dy;
    #pragma unroll
    for (int cc = 0; cc < 32; cc += 4) {
        float4 a = *(const float4*)(z11 + cc);
        float4 b = *(const float4*)(z21 + cc);
        float4 c = *(const float4*)(z12 + cc);
        float4 d = *(const float4*)(z22 + cc);
        float v0, v1, v2, v3;
        { float R1 = a.x*omdx + b.x*dx, R2 = c.x*omdx + d.x*dx; v0 = R1*omdy + R2*dy; }
        { float R1 = a.y*omdx + b.y*dx, R2 = c.y*omdx + d.y*dx; v1 = R1*omdy + R2*dy; }
        { float R1 = a.z*omdx + b.z*dx, R2 = c.z*omdx + d.z*dx; v2 = R1*omdy + R2*dy; }
        { float R1 = a.w*omdx + b.w*dx, R2 = c.w*omdx + d.w*dx; v3 = R1*omdy + R2*dy; }
        g_key2[base0 + (long)(cc + 0) * (512*256)] = v0;
        g_key2[base0 + (long)(cc + 1) * (512*256)] = v1;
        g_key2[base0 + (long)(cc + 2) * (512*256)] = v2;
        g_key2[base0 + (long)(cc + 3) * (512*256)] = v3;
    }
}

// ---------------- 3) query = [q_z | Q@w2^T + b2]; also write q_z into output ----------------
__global__ void query_kernel(const float* __restrict__ Q,
                             const float* __restrict__ q_z,
                             const float* __restrict__ w2,
                             const float* __restrict__ b2,
                             float* __restrict__ outp) {
    int b = blockIdx.x, t = threadIdx.x;
    if (t < 256) {
        float v = q_z[(long)b * 256 + t];
        g_query[(long)b * En + t] = v;
        outp[(long)b * 768 + t] = v;
    } else {
        int h = t - 256;
        float v = Q[b*3+0]*w2[h*3+0] + Q[b*3+1]*w2[h*3+1] + Q[b*3+2]*w2[h*3+2] + b2[h];
        g_query[(long)b * En + t] = v;
    }
}

// ---------------- register-tiled GEMM: C[m][n] = sum_k A[m*lda+k]*B[n*ldbn+k*ldbk] + bias[n] ----
// 64x64 tile, KC=16, 256 threads, 4x4 micro-tile with k-major smem + float4 LDS.
__global__ __launch_bounds__(256)
void gemm_kernel(const float* __restrict__ A, int lda, long sA,
                 const float* __restrict__ B, int ldbn, int ldbk, long sB,
                 float* __restrict__ Cp, int ldc, long sC,
                 const float* __restrict__ bias, long sBias,
                 int M, int N, int K) {
    int batch = blockIdx.z;
    A += (long)batch * sA;
    B += (long)batch * sB;
    Cp += (long)batch * sC;
    if (bias) bias += (long)batch * sBias;

    __shared__ float As[16][68];
    __shared__ float Bs[16][68];
    int tid = threadIdx.x;
    int tx = tid & 15, ty = tid >> 4;
    int m0 = blockIdx.y * 64, n0 = blockIdx.x * 64;
    float acc[4][4] = {};

    for (int k0 = 0; k0 < K; k0 += 16) {
        {   // A tile 64x16 -> k-major
            int rr = tid >> 2, c4 = (tid & 3) * 4;
            float4 v = *(const float4*)(&A[(long)(m0 + rr) * lda + k0 + c4]);
            As[c4+0][rr] = v.x; As[c4+1][rr] = v.y; As[c4+2][rr] = v.z; As[c4+3][rr] = v.w;
        }
        if (ldbk == 1) {
            int rr = tid >> 2, c4 = (tid & 3) * 4;
            float4 v = *(const float4*)(&B[(long)(n0 + rr) * ldbn + k0 + c4]);
            Bs[c4+0][rr] = v.x; Bs[c4+1][rr] = v.y; Bs[c4+2][rr] = v.z; Bs[c4+3][rr] = v.w;
        } else { // ldbn == 1, k strided
            #pragma unroll
            for (int q = 0; q < 4; q++) {
                int idx = tid + 256 * q;
                int nn = idx & 63, kk = idx >> 6;
                Bs[kk][nn] = B[(long)(n0 + nn) * ldbn + (long)(k0 + kk) * ldbk];
            }
        }
        __syncthreads();
        #pragma unroll
        for (int k = 0; k < 16; k++) {
            float4 av = *(const float4*)(&As[k][ty*4]);
            float4 bv = *(const float4*)(&Bs[k][tx*4]);
            float a[4] = {av.x, av.y, av.z, av.w};
            float b[4] = {bv.x, bv.y, bv.z, bv.w};
            #pragma unroll
            for (int i = 0; i < 4; i++)
                #pragma unroll
                for (int j = 0; j < 4; j++)
                    acc[i][j] += a[i] * b[j];
        }
        __syncthreads();
    }
    #pragma unroll
    for (int i = 0; i < 4; i++) {
        int m = m0 + ty*4 + i;
        #pragma unroll
        for (int j = 0; j < 4; j++) {
            int n = n0 + tx*4 + j;
            float v = acc[i][j];
            if (bias) v += bias[n];
            Cp[(long)m * ldc + n] = v;
        }
    }
}

// ---------------- 4) fused attention (key cols [256,512) generated in-kernel) ----------------
#define KS  516   /* skey row stride (floats) */
#define SQS 516   /* sq   row stride */

__global__ __launch_bounds__(512)
void attn_kernel(const float* __restrict__ qk, const float* __restrict__ key2,
                 const float* __restrict__ r, const float* __restrict__ w1,
                 const float* __restrict__ b1, float* __restrict__ ctx) {
    extern __shared__ float smf[];
    float* skey = smf;                 // 64*516
    float* sq   = smf + 33024;         // 8*516
    float* red  = smf + 37152;         // 16*512
    float* sc   = smf + 45344;         // 512
    float* sa   = smf + 45856;         // 512
    float* smax = smf + 46368;         // 8
    float* srs  = smf + 46376;         // 8
    float* rxy  = smf + 46384;         // 128
    float* pm   = smf + 46512;         // 64
    float* ps   = smf + 46576;         // 64
    float* w1e  = smf + 46640;         // 256
    float* w1o  = smf + 46896;         // 256
    float* b1s  = smf + 47152;         // 256  -> total 47408 floats

    int b = blockIdx.x, t = threadIdx.x;

    if (t < 128) rxy[t] = r[b*128 + t];
    if (t >= 128 && t < 384) {
        int h = t - 128;
        w1e[h] = w1[2*h]; w1o[h] = w1[2*h+1]; b1s[h] = b1[h];
    }
    // load interp half of key: rows b*64..b*64+63, 256 cols
    const float* keyb = key2 + (long)b * (64*256);
    #pragma unroll
    for (int it = 0; it < 8; it++) {
        int idx = t + 512*it;                 // 4096 float4
        int row = idx >> 6, c4 = (idx & 63) * 4;
        float4 v = *(const float4*)(keyb + row*256 + c4);
        *(float4*)(skey + row*KS + c4) = v;
    }
    // load qk[b] (8x512)
    {
        const float4* src = (const float4*)(qk + (long)b * 4096);
        #pragma unroll
        for (int it = 0; it < 2; it++) {
            int idx = t + 512*it;
            int row = idx >> 7, c = idx & 127;
            *(float4*)(sq + row*SQS + c*4) = src[row*128 + c];
        }
    }
    __syncthreads();

    // generate r_proj cols [256,512) directly into smem
    #pragma unroll
    for (int rep = 0; rep < 8; rep++) {
        int idx = t + 512*rep;                // 4096 float4 positions
        int k = idx >> 6, h4 = (idx & 63) * 4;
        float x = rxy[2*k], y = rxy[2*k+1];
        float4 we = *(const float4*)(w1e + h4);
        float4 wo = *(const float4*)(w1o + h4);
        float4 bb = *(const float4*)(b1s + h4);
        float4 o;
        o.x = x*we.x + y*wo.x + bb.x;
        o.y = x*we.y + y*wo.y + bb.y;
        o.z = x*we.z + y*wo.z + bb.z;
        o.w = x*we.w + y*wo.w + bb.w;
        *(float4*)(skey + k*KS + 256 + h4) = o;
    }
    __syncthreads();

    // ---- phase 1: scores. 16-way k-split over j, 4h x 4k micro-tiles ----
    {
        int ks = t >> 5, lane = t & 31;
        int hq = lane >> 4, kq = lane & 15;
        int h0 = hq * 4;
        float acc[4][4] = {};
        int jbase = ks * 32;
        #pragma unroll
        for (int s = 0; s < 8; s++) {
            int jj = jbase + s*4;
            float4 a0 = *(const float4*)(sq + (h0+0)*SQS + jj);
            float4 a1 = *(const float4*)(sq + (h0+1)*SQS + jj);
            float4 a2 = *(const float4*)(sq + (h0+2)*SQS + jj);
            float4 a3 = *(const float4*)(sq + (h0+3)*SQS + jj);
            float4 b0 = *(const float4*)(skey + (kq     )*KS + jj);
            float4 b1v= *(const float4*)(skey + (kq + 16)*KS + jj);
            float4 b2 = *(const float4*)(skey + (kq + 32)*KS + jj);
            float4 b3 = *(const float4*)(skey + (kq + 48)*KS + jj);
            float4 A4[4] = {a0,a1,a2,a3};
            float4 B4[4] = {b0,b1v,b2,b3};
            #pragma unroll
            for (int hi = 0; hi < 4; hi++)
                #pragma unroll
                for (int ki = 0; ki < 4; ki++)
                    acc[hi][ki] += A4[hi].x*B4[ki].x + A4[hi].y*B4[ki].y
                                 + A4[hi].z*B4[ki].z + A4[hi].w*B4[ki].w;
        }
        #pragma unroll
        for (int hi = 0; hi < 4; hi++)
            #pragma unroll
            for (int ki = 0; ki < 4; ki++)
                red[ks*512 + (h0+hi)*64 + ki*16 + kq] = acc[hi][ki];
    }
    __syncthreads();
    {
        float s = 0.0f;
        #pragma unroll
        for (int i = 0; i < 16; i++) s += red[i*512 + t];
        sc[t] = s * 0.125f;                    // / sqrt(64)
    }
    __syncthreads();

    // ---- softmax over k per head ----
    if (t < 64) {
        int h = t >> 3, part = t & 7;
        float m = -1e30f;
        #pragma unroll
        for (int q = 0; q < 8; q++) m = fmaxf(m, sc[h*64 + part*8 + q]);
        pm[t] = m;
    }
    __syncthreads();
    if (t < 8) {
        float m = -1e30f;
        #pragma unroll
        for (int q = 0; q < 8; q++) m = fmaxf(m, pm[t*8 + q]);
        smax[t] = m;
    }
    __syncthreads();
    if (t < 64) {
        int h = t >> 3, part = t & 7;
        float s = 0.0f;
        #pragma unroll
        for (int q = 0; q < 8; q++) s += expf(sc[h*64 + part*8 + q] - smax[h]);
        ps[t] = s;
    }
    __syncthreads();
    if (t < 8) {
        float s = 0.0f;
        #pragma unroll
        for (int q = 0; q < 8; q++) s += ps[t*8 + q];
        srs[t] = 1.0f / s;
    }
    __syncthreads();
    sa[t] = expf(sc[t] - smax[t >> 6]) * srs[t >> 6];
    __syncthreads();

    // ---- phase 3: ctx = attn @ skey. 4h x 4j micro-tiles, 256 threads ----
    if (t < 256) {
        int hq = t >> 7, jq = t & 127;
        int h0 = hq * 4, j0 = jq * 4;
        float acc[4][4] = {};
        #pragma unroll 4
        for (int k = 0; k < 64; k++) {
            float4 bv = *(const float4*)(skey + k*KS + j0);
            float a0 = sa[(h0+0)*64 + k];
            float a1 = sa[(h0+1)*64 + k];
            float a2 = sa[(h0+2)*64 + k];
            float a3 = sa[(h0+3)*64 + k];
            acc[0][0] += a0*bv.x; acc[0][1] += a0*bv.y; acc[0][2] += a0*bv.z; acc[0][3] += a0*bv.w;
            acc[1][0] += a1*bv.x; acc[1][1] += a1*bv.y; acc[1][2] += a1*bv.z; acc[1][3] += a1*bv.w;
            acc[2][0] += a2*bv.x; acc[2][1] += a2*bv.y; acc[2][2] += a2*bv.z; acc[2][3] += a2*bv.w;
            acc[3][0] += a3*bv.x; acc[3][1] += a3*bv.y; acc[3][2] += a3*bv.z; acc[3][3] += a3*bv.w;
        }
        float* ctxb = ctx + (long)b * 4096;
        #pragma unroll
        for (int hi = 0; hi < 4; hi++) {
            float4 o = make_float4(acc[hi][0], acc[hi][1], acc[hi][2], acc[hi][3]);
            *(float4*)(ctxb + (h0+hi)*512 + j0) = o;
        }
    }
}

#define ATTN_SMEM (47408 * 4)

// ---------------- host launcher ----------------
extern "C" void kernel_launch(void* const* d_in, const int* in_sizes, int n_in,
                              void* d_out, int out_size) {
    const float* Z          = (const float*)d_in[0];
    const float* Q          = (const float*)d_in[1];
    const float* q_z        = (const float*)d_in[2];
    const float* r          = (const float*)d_in[3];
    const float* w1         = (const float*)d_in[4];
    const float* b1         = (const float*)d_in[5];
    const float* w2         = (const float*)d_in[6];
    const float* b2         = (const float*)d_in[7];
    const float* in_proj_w  = (const float*)d_in[8];
    const float* in_proj_b  = (const float*)d_in[9];
    const float* out_proj_w = (const float*)d_in[10];
    const float* out_proj_b = (const float*)d_in[11];
    float* outp = (float*)d_out;

    float *pKey2, *pQuery, *pQl, *pQk, *pCtx, *pOut1;
    cudaGetSymbolAddress((void**)&pKey2,  g_key2);
    cudaGetSymbolAddress((void**)&pQuery, g_query);
    cudaGetSymbolAddress((void**)&pQl,    g_ql);
    cudaGetSymbolAddress((void**)&pQk,    g_qk);
    cudaGetSymbolAddress((void**)&pCtx,   g_ctx);
    cudaGetSymbolAddress((void**)&pOut1,  g_out1);

    cudaFuncSetAttribute(attn_kernel,
                         cudaFuncAttributeMaxDynamicSharedMemorySize, ATTN_SMEM);

    // 1) transpose Z -> Zt
    transpose_kernel<<<dim3((HWn*HWn)/32, Cn/32), dim3(32, 8)>>>(Z);

    // 2) bilinear interp -> key2
    interp_kernel<<<dim3(NPn/256, Cn/32), 256>>>(r);

    // 3) query = [q_z | Q@w2^T + b2]; also write q_z half of output
    query_kernel<<<SQn, 512>>>(Q, q_z, w2, b2, outp);

    // 4) ql = query @ Wq^T + bq
    gemm_kernel<<<dim3(En/64, SQn/64, 1), 256>>>(
        pQuery, En, 0L,
        in_proj_w, En, 1, 0L,
        pQl, En, 0L,
        in_proj_b, 0L,
        SQn, En, En);

    // 5) qk[b][h][n] = sum_d ql[b][h*64+d] * Wk[h*64+d][n]
    gemm_kernel<<<dim3(En/64, SQn/64, NHn), 256>>>(
        pQl, En, (long)HDn,
        in_proj_w + (long)En*En, 1, En, (long)HDn*En,
        pQk, NHn*En, (long)En,
        (const float*)0, 0L,
        SQn, En, HDn);

    // 6) fused attention (generates r_proj cols in-kernel)
    attn_kernel<<<SQn, 512, ATTN_SMEM>>>(pQk, pKey2, r, w1, b1, pCtx);

    // 7) out1[b][h*64+d] = ctx[b][h][:] . Wv[h*64+d][:] + bv
    gemm_kernel<<<dim3(HDn/64, SQn/64, NHn), 256>>>(
        pCtx, NHn*En, (long)En,
        in_proj_w + (long)2*En*En, En, 1, (long)HDn*En,
        pOut1, En, (long)HDn,
        in_proj_b + (long)2*En, (long)HDn,
        SQn, HDn, En);

    // 8) final out_proj into d_out cols [256,768)
    gemm_kernel<<<dim3(En/64, SQn/64, 1), 256>>>(
        pOut1, En, 0L,
        out_proj_w, En, 1, 0L,
        outp + 256, 768, 0L,
        out_proj_b, 0L,
        SQn, En, En);
}

// round 6
// speedup vs baseline: 1.6992x; 1.1916x over previous
#include <cuda_runtime.h>
#include <math.h>

#define SQn   2048
#define SKn   64
#define Cn    256
#define HWn   256
#define En    512
#define NPn   (SQn*SKn)
#define NHn   8
#define HDn   64

// ---------------- scratch ----------------
__device__ float g_Zt[(size_t)Cn*HWn*HWn];      // 67 MB   Zt[x][y][c]
__device__ float g_key2[(size_t)NPn*256];       // 134 MB  interp half of key (131072 x 256)
__device__ float g_query[(size_t)SQn*En];
__device__ float g_ql[(size_t)SQn*En];
__device__ float g_qk[(size_t)SQn*NHn*En];      // qk[b][h][j]
__device__ float g_ctx[(size_t)SQn*NHn*En];     // ctx[b][h][j]
__device__ float g_out1[(size_t)SQn*En];

// ---------------- 1) transpose Z (C, HW*HW) -> Zt (HW*HW, C) ----------------
__global__ void transpose_kernel(const float* __restrict__ Z) {
    __shared__ float tile[32][33];
    int xy0 = blockIdx.x * 32;
    int c0  = blockIdx.y * 32;
    int tx = threadIdx.x, ty = threadIdx.y;   // 32 x 8
    #pragma unroll
    for (int i = 0; i < 32; i += 8)
        tile[ty + i][tx] = Z[(long)(c0 + ty + i) * (HWn*HWn) + xy0 + tx];
    __syncthreads();
    #pragma unroll
    for (int i = 0; i < 32; i += 8)
        g_Zt[(long)(xy0 + ty + i) * Cn + c0 + tx] = tile[tx][ty + i];
}

// ---------------- 2) bilinear interp -> key2 (131072 x 256, scrambled rows) ----------------
__global__ void interp_kernel(const float* __restrict__ r) {
    int p  = blockIdx.x * 256 + threadIdx.x;
    int c0 = blockIdx.y * 32;
    float x = r[2*p], y = r[2*p + 1];
    int x1 = (int)x, y1 = (int)y;
    float dx = x - (float)x1, dy = y - (float)y1;
    const float* z11 = g_Zt + ((long)x1 * HWn + y1) * Cn + c0;
    const float* z12 = z11 + Cn;
    const float* z21 = z11 + (long)HWn*Cn;
    const float* z22 = z21 + Cn;
    long base0 = ((long)c0 * 512 + (p >> 8)) * 256 + (p & 255);
    float omdx = 1.0f - dx, omdy = 1.0f - dy;
    #pragma unroll
    for (int cc = 0; cc < 32; cc += 4) {
        float4 a = *(const float4*)(z11 + cc);
        float4 b = *(const float4*)(z21 + cc);
        float4 c = *(const float4*)(z12 + cc);
        float4 d = *(const float4*)(z22 + cc);
        float v0, v1, v2, v3;
        { float R1 = a.x*omdx + b.x*dx, R2 = c.x*omdx + d.x*dx; v0 = R1*omdy + R2*dy; }
        { float R1 = a.y*omdx + b.y*dx, R2 = c.y*omdx + d.y*dx; v1 = R1*omdy + R2*dy; }
        { float R1 = a.z*omdx + b.z*dx, R2 = c.z*omdx + d.z*dx; v2 = R1*omdy + R2*dy; }
        { float R1 = a.w*omdx + b.w*dx, R2 = c.w*omdx + d.w*dx; v3 = R1*omdy + R2*dy; }
        g_key2[base0 + (long)(cc + 0) * (512*256)] = v0;
        g_key2[base0 + (long)(cc + 1) * (512*256)] = v1;
        g_key2[base0 + (long)(cc + 2) * (512*256)] = v2;
        g_key2[base0 + (long)(cc + 3) * (512*256)] = v3;
    }
}

// ---------------- 3) query = [q_z | Q@w2^T + b2]; also write q_z into output ----------------
__global__ void query_kernel(const float* __restrict__ Q,
                             const float* __restrict__ q_z,
                             const float* __restrict__ w2,
                             const float* __restrict__ b2,
                             float* __restrict__ outp) {
    int b = blockIdx.x, t = threadIdx.x;
    if (t < 256) {
        float v = q_z[(long)b * 256 + t];
        g_query[(long)b * En + t] = v;
        outp[(long)b * 768 + t] = v;
    } else {
        int h = t - 256;
        float v = Q[b*3+0]*w2[h*3+0] + Q[b*3+1]*w2[h*3+1] + Q[b*3+2]*w2[h*3+2] + b2[h];
        g_query[(long)b * En + t] = v;
    }
}

// ---------------- GEMM: 128x64 tile, 256 thr, 8x4 micro, reg-prefetch dbuf ----------------
// C[m][n] = sum_k A[m*lda+k] * B[n*ldbn + k*ldbk] + bias[n]
__global__ __launch_bounds__(256)
void gemm_kernel(const float* __restrict__ A, int lda, long sA,
                 const float* __restrict__ B, int ldbn, int ldbk, long sB,
                 float* __restrict__ Cp, int ldc, long sC,
                 const float* __restrict__ bias, long sBias,
                 int M, int N, int K) {
    int batch = blockIdx.z;
    A  += (long)batch * sA;
    B  += (long)batch * sB;
    Cp += (long)batch * sC;
    if (bias) bias += (long)batch * sBias;

    __shared__ float As[16][132];
    __shared__ float Bs[16][68];
    int t = threadIdx.x;
    int tx = t & 15, ty = t >> 4;
    int m0 = blockIdx.y * 128, n0 = blockIdx.x * 64;

    int ar = t >> 2, ac = (t & 3) * 4;          // loader coords
    const bool bvec = (ldbk == 1);
    const float* Abase = A + (long)(m0 + ar) * lda + ac;

    float4 ra0, ra1, rb;
    float rbs[4];
    // prefetch chunk 0
    ra0 = *(const float4*)(Abase);
    ra1 = *(const float4*)(Abase + (long)64 * lda);
    if (bvec) {
        rb = *(const float4*)(B + (long)(n0 + ar) * ldbn + ac);
    } else {
        #pragma unroll
        for (int q = 0; q < 4; q++) {
            int idx = t + 256*q; int nn = idx & 63, kk = idx >> 6;
            rbs[q] = B[(long)(n0 + nn) + (long)kk * ldbk];
        }
    }

    float acc[8][4] = {};
    for (int k0 = 0; k0 < K; k0 += 16) {
        As[ac+0][ar]    = ra0.x; As[ac+1][ar]    = ra0.y; As[ac+2][ar]    = ra0.z; As[ac+3][ar]    = ra0.w;
        As[ac+0][ar+64] = ra1.x; As[ac+1][ar+64] = ra1.y; As[ac+2][ar+64] = ra1.z; As[ac+3][ar+64] = ra1.w;
        if (bvec) {
            Bs[ac+0][ar] = rb.x; Bs[ac+1][ar] = rb.y; Bs[ac+2][ar] = rb.z; Bs[ac+3][ar] = rb.w;
        } else {
            #pragma unroll
            for (int q = 0; q < 4; q++) {
                int idx = t + 256*q; int nn = idx & 63, kk = idx >> 6;
                Bs[kk][nn] = rbs[q];
            }
        }
        __syncthreads();
        if (k0 + 16 < K) {   // prefetch next chunk (overlaps compute)
            const float* An = Abase + k0 + 16;
            ra0 = *(const float4*)(An);
            ra1 = *(const float4*)(An + (long)64 * lda);
            if (bvec) {
                rb = *(const float4*)(B + (long)(n0 + ar) * ldbn + k0 + 16 + ac);
            } else {
                #pragma unroll
                for (int q = 0; q < 4; q++) {
                    int idx = t + 256*q; int nn = idx & 63, kk = idx >> 6;
                    rbs[q] = B[(long)(n0 + nn) + (long)(k0 + 16 + kk) * ldbk];
                }
            }
        }
        #pragma unroll
        for (int k = 0; k < 16; k++) {
            float4 a0 = *(const float4*)(&As[k][ty*8]);
            float4 a1 = *(const float4*)(&As[k][ty*8+4]);
            float4 b  = *(const float4*)(&Bs[k][tx*4]);
            float am[8] = {a0.x,a0.y,a0.z,a0.w,a1.x,a1.y,a1.z,a1.w};
            float bn[4] = {b.x,b.y,b.z,b.w};
            #pragma unroll
            for (int i = 0; i < 8; i++)
                #pragma unroll
                for (int j = 0; j < 4; j++)
                    acc[i][j] += am[i]*bn[j];
        }
        __syncthreads();
    }
    float4 bb = make_float4(0.f,0.f,0.f,0.f);
    if (bias) bb = *(const float4*)(bias + n0 + tx*4);
    #pragma unroll
    for (int i = 0; i < 8; i++) {
        int m = m0 + ty*8 + i;
        float4 o = make_float4(acc[i][0]+bb.x, acc[i][1]+bb.y, acc[i][2]+bb.z, acc[i][3]+bb.w);
        *(float4*)(&Cp[(long)m * ldc + n0 + tx*4]) = o;
    }
}

// ---------------- 4) fused attention, smem-slim (occupancy 2) ----------------
// smem (floats): skey 64x268 | sq 8x516 | red 8x512 | sc 512 | sa 512 |
//                smax 8 | srs 8 | rxy 128 | w1e 256 | w1o 256 | b1s 256
#define SKS 268
#define SQS 516
#define OFF_SQ   17152
#define OFF_RED  21280
#define OFF_SC   25376
#define OFF_SA   25888
#define OFF_SMAX 26400
#define OFF_SRS  26408
#define OFF_RXY  26416
#define OFF_W1E  26544
#define OFF_W1O  26800
#define OFF_B1S  27056
#define ATTN_FLTS 27312
#define ATTN_SMEM (ATTN_FLTS*4)

__global__ __launch_bounds__(512, 2)
void attn_kernel(const float* __restrict__ qk, const float* __restrict__ key2,
                 const float* __restrict__ r, const float* __restrict__ w1,
                 const float* __restrict__ b1, float* __restrict__ ctx) {
    extern __shared__ float smf[];
    float* skey = smf;
    float* sq   = smf + OFF_SQ;
    float* red  = smf + OFF_RED;
    float* sc   = smf + OFF_SC;
    float* sa   = smf + OFF_SA;
    float* smax = smf + OFF_SMAX;
    float* srs  = smf + OFF_SRS;
    float* rxy  = smf + OFF_RXY;
    float* w1e  = smf + OFF_W1E;
    float* w1o  = smf + OFF_W1O;
    float* b1s  = smf + OFF_B1S;

    int b = blockIdx.x, t = threadIdx.x;

    // ---- loads: key2 (64x256), qk (8x512), r/w1/b1 staging ----
    const float* keyb = key2 + (long)b * (64*256);
    #pragma unroll
    for (int q = 0; q < 8; q++) {
        int idx = t + 512*q;
        int row = idx >> 6, c4 = (idx & 63) * 4;
        *(float4*)(skey + row*SKS + c4) = *(const float4*)(keyb + row*256 + c4);
    }
    {
        const float4* qsrc = (const float4*)(qk + (long)b * 4096);
        #pragma unroll
        for (int q = 0; q < 2; q++) {
            int idx = t + 512*q;
            int row = idx >> 7, c = idx & 127;
            *(float4*)(sq + row*SQS + c*4) = qsrc[row*128 + c];
        }
    }
    if (t < 128) {
        rxy[t] = r[b*128 + t];
    } else if (t < 384) {
        int h = t - 128;
        w1e[h] = w1[2*h]; w1o[h] = w1[2*h+1]; b1s[h] = b1[h];
    }
    __syncthreads();

    // ---- phase 1: scores (256 threads, 8 j-slices, 4h x 4k micro) ----
    if (t < 256) {
        int s = t >> 5, lane = t & 31;
        int hq = lane >> 4, kq = lane & 15;
        int h0 = hq * 4, jb = s * 32;
        float acc[4][4] = {};
        // interp half (skey in smem)
        #pragma unroll
        for (int st = 0; st < 8; st++) {
            int jj = jb + st*4;
            float4 a0 = *(const float4*)(sq + (h0+0)*SQS + jj);
            float4 a1 = *(const float4*)(sq + (h0+1)*SQS + jj);
            float4 a2 = *(const float4*)(sq + (h0+2)*SQS + jj);
            float4 a3 = *(const float4*)(sq + (h0+3)*SQS + jj);
            #pragma unroll
            for (int m = 0; m < 4; m++) {
                float4 bv = *(const float4*)(skey + (kq + 16*m)*SKS + jj);
                acc[0][m] += a0.x*bv.x + a0.y*bv.y + a0.z*bv.z + a0.w*bv.w;
                acc[1][m] += a1.x*bv.x + a1.y*bv.y + a1.z*bv.z + a1.w*bv.w;
                acc[2][m] += a2.x*bv.x + a2.y*bv.y + a2.z*bv.z + a2.w*bv.w;
                acc[3][m] += a3.x*bv.x + a3.y*bv.y + a3.z*bv.z + a3.w*bv.w;
            }
        }
        // r_proj half (generated in registers)
        #pragma unroll
        for (int st = 0; st < 8; st++) {
            int w = jb + st*4, jj = 256 + w;
            float4 a0 = *(const float4*)(sq + (h0+0)*SQS + jj);
            float4 a1 = *(const float4*)(sq + (h0+1)*SQS + jj);
            float4 a2 = *(const float4*)(sq + (h0+2)*SQS + jj);
            float4 a3 = *(const float4*)(sq + (h0+3)*SQS + jj);
            float4 we = *(const float4*)(w1e + w);
            float4 wo = *(const float4*)(w1o + w);
            float4 bc = *(const float4*)(b1s + w);
            #pragma unroll
            for (int m = 0; m < 4; m++) {
                int k = kq + 16*m;
                float x = rxy[2*k], y = rxy[2*k+1];
                float4 bv;
                bv.x = fmaf(x, we.x, fmaf(y, wo.x, bc.x));
                bv.y = fmaf(x, we.y, fmaf(y, wo.y, bc.y));
                bv.z = fmaf(x, we.z, fmaf(y, wo.z, bc.z));
                bv.w = fmaf(x, we.w, fmaf(y, wo.w, bc.w));
                acc[0][m] += a0.x*bv.x + a0.y*bv.y + a0.z*bv.z + a0.w*bv.w;
                acc[1][m] += a1.x*bv.x + a1.y*bv.y + a1.z*bv.z + a1.w*bv.w;
                acc[2][m] += a2.x*bv.x + a2.y*bv.y + a2.z*bv.z + a2.w*bv.w;
                acc[3][m] += a3.x*bv.x + a3.y*bv.y + a3.z*bv.z + a3.w*bv.w;
            }
        }
        #pragma unroll
        for (int hi = 0; hi < 4; hi++)
            #pragma unroll
            for (int m = 0; m < 4; m++)
                red[s*512 + (h0+hi)*64 + m*16 + kq] = acc[hi][m];
    }
    __syncthreads();
    {
        float v = 0.f;
        #pragma unroll
        for (int s2 = 0; s2 < 8; s2++) v += red[s2*512 + t];
        sc[t] = v * 0.125f;                 // / sqrt(64)
    }
    __syncthreads();

    // ---- softmax over k per head: one warp, shuffles ----
    if (t < 32) {
        int h = t >> 2, seg = t & 3;
        const float* p = sc + h*64 + seg*16;
        float mx = p[0];
        #pragma unroll
        for (int i = 1; i < 16; i++) mx = fmaxf(mx, p[i]);
        mx = fmaxf(mx, __shfl_xor_sync(0xffffffffu, mx, 1));
        mx = fmaxf(mx, __shfl_xor_sync(0xffffffffu, mx, 2));
        float sm = 0.f;
        #pragma unroll
        for (int i = 0; i < 16; i++) sm += __expf(p[i] - mx);
        sm += __shfl_xor_sync(0xffffffffu, sm, 1);
        sm += __shfl_xor_sync(0xffffffffu, sm, 2);
        if (seg == 0) { smax[h] = mx; srs[h] = 1.0f / sm; }
    }
    __syncthreads();
    sa[t] = __expf(sc[t] - smax[t >> 6]) * srs[t >> 6];
    __syncthreads();

    // ---- phase 3: ctx = attn @ key (256 threads, 4h x 4j micro) ----
    if (t < 256) {
        int hq = t >> 7, jq = t & 127;
        int h0 = hq * 4, j0 = jq * 4;
        const float* sa0 = sa + (h0+0)*64;
        const float* sa1 = sa + (h0+1)*64;
        const float* sa2 = sa + (h0+2)*64;
        const float* sa3 = sa + (h0+3)*64;
        float acc[4][4] = {};
        if (j0 < 256) {
            #pragma unroll 8
            for (int k = 0; k < 64; k++) {
                float4 bv = *(const float4*)(skey + k*SKS + j0);
                float a0 = sa0[k], a1 = sa1[k], a2 = sa2[k], a3 = sa3[k];
                acc[0][0] += a0*bv.x; acc[0][1] += a0*bv.y; acc[0][2] += a0*bv.z; acc[0][3] += a0*bv.w;
                acc[1][0] += a1*bv.x; acc[1][1] += a1*bv.y; acc[1][2] += a1*bv.z; acc[1][3] += a1*bv.w;
                acc[2][0] += a2*bv.x; acc[2][1] += a2*bv.y; acc[2][2] += a2*bv.z; acc[2][3] += a2*bv.w;
                acc[3][0] += a3*bv.x; acc[3][1] += a3*bv.y; acc[3][2] += a3*bv.z; acc[3][3] += a3*bv.w;
            }
        } else {
            int w = j0 - 256;
            float4 we = *(const float4*)(w1e + w);
            float4 wo = *(const float4*)(w1o + w);
            float4 bc = *(const float4*)(b1s + w);
            #pragma unroll 4
            for (int k = 0; k < 64; k++) {
                float x = rxy[2*k], y = rxy[2*k+1];
                float4 bv;
                bv.x = fmaf(x, we.x, fmaf(y, wo.x, bc.x));
                bv.y = fmaf(x, we.y, fmaf(y, wo.y, bc.y));
                bv.z = fmaf(x, we.z, fmaf(y, wo.z, bc.z));
                bv.w = fmaf(x, we.w, fmaf(y, wo.w, bc.w));
                float a0 = sa0[k], a1 = sa1[k], a2 = sa2[k], a3 = sa3[k];
                acc[0][0] += a0*bv.x; acc[0][1] += a0*bv.y; acc[0][2] += a0*bv.z; acc[0][3] += a0*bv.w;
                acc[1][0] += a1*bv.x; acc[1][1] += a1*bv.y; acc[1][2] += a1*bv.z; acc[1][3] += a1*bv.w;
                acc[2][0] += a2*bv.x; acc[2][1] += a2*bv.y; acc[2][2] += a2*bv.z; acc[2][3] += a2*bv.w;
                acc[3][0] += a3*bv.x; acc[3][1] += a3*bv.y; acc[3][2] += a3*bv.z; acc[3][3] += a3*bv.w;
            }
        }
        float* ctxb = ctx + (long)b * 4096;
        #pragma unroll
        for (int hi = 0; hi < 4; hi++) {
            float4 o = make_float4(acc[hi][0], acc[hi][1], acc[hi][2], acc[hi][3]);
            *(float4*)(ctxb + (h0+hi)*512 + j0) = o;
        }
    }
}

// ---------------- host launcher ----------------
extern "C" void kernel_launch(void* const* d_in, const int* in_sizes, int n_in,
                              void* d_out, int out_size) {
    const float* Z          = (const float*)d_in[0];
    const float* Q          = (const float*)d_in[1];
    const float* q_z        = (const float*)d_in[2];
    const float* r          = (const float*)d_in[3];
    const float* w1         = (const float*)d_in[4];
    const float* b1         = (const float*)d_in[5];
    const float* w2         = (const float*)d_in[6];
    const float* b2         = (const float*)d_in[7];
    const float* in_proj_w  = (const float*)d_in[8];
    const float* in_proj_b  = (const float*)d_in[9];
    const float* out_proj_w = (const float*)d_in[10];
    const float* out_proj_b = (const float*)d_in[11];
    float* outp = (float*)d_out;

    float *pKey2, *pQuery, *pQl, *pQk, *pCtx, *pOut1;
    cudaGetSymbolAddress((void**)&pKey2,  g_key2);
    cudaGetSymbolAddress((void**)&pQuery, g_query);
    cudaGetSymbolAddress((void**)&pQl,    g_ql);
    cudaGetSymbolAddress((void**)&pQk,    g_qk);
    cudaGetSymbolAddress((void**)&pCtx,   g_ctx);
    cudaGetSymbolAddress((void**)&pOut1,  g_out1);

    cudaFuncSetAttribute(attn_kernel,
                         cudaFuncAttributeMaxDynamicSharedMemorySize, ATTN_SMEM);

    // 1) transpose Z -> Zt
    transpose_kernel<<<dim3((HWn*HWn)/32, Cn/32), dim3(32, 8)>>>(Z);

    // 2) bilinear interp -> key2
    interp_kernel<<<dim3(NPn/256, Cn/32), 256>>>(r);

    // 3) query = [q_z | Q@w2^T + b2]; also write q_z half of output
    query_kernel<<<SQn, 512>>>(Q, q_z, w2, b2, outp);

    // 4) ql = query @ Wq^T + bq
    gemm_kernel<<<dim3(En/64, SQn/128, 1), 256>>>(
        pQuery, En, 0L,
        in_proj_w, En, 1, 0L,
        pQl, En, 0L,
        in_proj_b, 0L,
        SQn, En, En);

    // 5) qk[b][h][n] = sum_d ql[b][h*64+d] * Wk[h*64+d][n]
    gemm_kernel<<<dim3(En/64, SQn/128, NHn), 256>>>(
        pQl, En, (long)HDn,
        in_proj_w + (long)En*En, 1, En, (long)HDn*En,
        pQk, NHn*En, (long)En,
        (const float*)0, 0L,
        SQn, En, HDn);

    // 6) fused attention (r_proj generated in-register)
    attn_kernel<<<SQn, 512, ATTN_SMEM>>>(pQk, pKey2, r, w1, b1, pCtx);

    // 7) out1[b][h*64+d] = ctx[b][h][:] . Wv[h*64+d][:] + bv
    gemm_kernel<<<dim3(HDn/64, SQn/128, NHn), 256>>>(
        pCtx, NHn*En, (long)En,
        in_proj_w + (long)2*En*En, En, 1, (long)HDn*En,
        pOut1, En, (long)HDn,
        in_proj_b + (long)2*En, (long)HDn,
        SQn, HDn, En);

    // 8) final out_proj into d_out cols [256,768)
    gemm_kernel<<<dim3(En/64, SQn/128, 1), 256>>>(
        pOut1, En, 0L,
        out_proj_w, En, 1, 0L,
        outp + 256, 768, 0L,
        out_proj_b, 0L,
        SQn, En, En);
}

// round 7
// speedup vs baseline: 1.9292x; 1.1353x over previous
#include <cuda_runtime.h>
#include <math.h>

#define SQn   2048
#define SKn   64
#define Cn    256
#define HWn   256
#define En    512
#define NPn   (SQn*SKn)
#define NHn   8
#define HDn   64

typedef unsigned long long u64;

__device__ __forceinline__ u64 fma2(u64 a, u64 b, u64 c) {
    u64 d;
    asm("fma.rn.f32x2 %0, %1, %2, %3;" : "=l"(d) : "l"(a), "l"(b), "l"(c));
    return d;
}
__device__ __forceinline__ u64 pack2(float lo, float hi) {
    u64 v;
    asm("mov.b64 %0, {%1, %2};" : "=l"(v) : "f"(lo), "f"(hi));
    return v;
}
__device__ __forceinline__ float2 unpack2(u64 v) {
    float lo, hi;
    asm("mov.b64 {%0, %1}, %2;" : "=f"(lo), "=f"(hi) : "l"(v));
    return make_float2(lo, hi);
}
__device__ __forceinline__ u64 splat2(float a) { return pack2(a, a); }

// ---------------- scratch ----------------
__device__ float g_Zt[(size_t)Cn*HWn*HWn];      // 67 MB   Zt[x][y][c]
__device__ float g_key2[(size_t)NPn*256];       // 134 MB  interp half of key
__device__ float g_query[(size_t)SQn*En];
__device__ float g_ql[(size_t)SQn*En];
__device__ float g_qk[(size_t)SQn*NHn*En];
__device__ float g_ctx[(size_t)SQn*NHn*En];
__device__ float g_out1[(size_t)SQn*En];

// ---------------- 1) transpose Z (C, HW*HW) -> Zt (HW*HW, C) ----------------
__global__ void transpose_kernel(const float* __restrict__ Z) {
    __shared__ float tile[32][33];
    int xy0 = blockIdx.x * 32;
    int c0  = blockIdx.y * 32;
    int tx = threadIdx.x, ty = threadIdx.y;   // 32 x 8
    #pragma unroll
    for (int i = 0; i < 32; i += 8)
        tile[ty + i][tx] = Z[(long)(c0 + ty + i) * (HWn*HWn) + xy0 + tx];
    __syncthreads();
    #pragma unroll
    for (int i = 0; i < 32; i += 8)
        g_Zt[(long)(xy0 + ty + i) * Cn + c0 + tx] = tile[tx][ty + i];
}

// ---------------- 2) bilinear interp, coalesced: warp->4 points, lane->channels ----------------
__global__ __launch_bounds__(256)
void interp_kernel(const float* __restrict__ r) {
    __shared__ float sres[256][33];   // [channel][point]
    __shared__ int   soff[32];
    __shared__ float sdx[32], sdy[32];
    int t = threadIdx.x;
    int p0 = blockIdx.x * 32;
    if (t < 32) {
        float x = r[2*(p0+t)], y = r[2*(p0+t)+1];
        int x1 = (int)x, y1 = (int)y;
        soff[t] = (x1*HWn + y1)*Cn;
        sdx[t] = x - (float)x1;
        sdy[t] = y - (float)y1;
    }
    __syncthreads();
    int wp = t >> 5, l = t & 31;
    #pragma unroll
    for (int pi = 0; pi < 4; pi++) {
        int pl = wp*4 + pi;
        long off = soff[pl];
        float dx = sdx[pl], dy = sdy[pl];
        float omdx = 1.0f - dx, omdy = 1.0f - dy;
        #pragma unroll
        for (int rep = 0; rep < 2; rep++) {
            int c = rep*128 + l*4;
            const float* z11 = g_Zt + off + c;
            float4 a  = *(const float4*)(z11);
            float4 cq = *(const float4*)(z11 + Cn);
            float4 b  = *(const float4*)(z11 + HWn*Cn);
            float4 d  = *(const float4*)(z11 + HWn*Cn + Cn);
            float v0 = (a.x*omdx + b.x*dx)*omdy + (cq.x*omdx + d.x*dx)*dy;
            float v1 = (a.y*omdx + b.y*dx)*omdy + (cq.y*omdx + d.y*dx)*dy;
            float v2 = (a.z*omdx + b.z*dx)*omdy + (cq.z*omdx + d.z*dx)*dy;
            float v3 = (a.w*omdx + b.w*dx)*omdy + (cq.w*omdx + d.w*dx)*dy;
            sres[c+0][pl] = v0;
            sres[c+1][pl] = v1;
            sres[c+2][pl] = v2;
            sres[c+3][pl] = v3;
        }
    }
    __syncthreads();
    // write phase: warp wp writes channels wp*32..+31; lane -> point (coalesced)
    long rowhi = (long)(p0 >> 8);
    int  colb  = p0 & 255;
    #pragma unroll
    for (int i = 0; i < 32; i++) {
        int c = wp*32 + i;
        g_key2[((long)c*512 + rowhi)*256 + colb + l] = sres[c][l];
    }
}

// ---------------- 3) query = [q_z | Q@w2^T + b2]; also write q_z into output ----------------
__global__ void query_kernel(const float* __restrict__ Q,
                             const float* __restrict__ q_z,
                             const float* __restrict__ w2,
                             const float* __restrict__ b2,
                             float* __restrict__ outp) {
    int b = blockIdx.x, t = threadIdx.x;
    if (t < 256) {
        float v = q_z[(long)b * 256 + t];
        g_query[(long)b * En + t] = v;
        outp[(long)b * 768 + t] = v;
    } else {
        int h = t - 256;
        float v = Q[b*3+0]*w2[h*3+0] + Q[b*3+1]*w2[h*3+1] + Q[b*3+2]*w2[h*3+2] + b2[h];
        g_query[(long)b * En + t] = v;
    }
}

// ---------------- GEMM: 128x64 tile, 256 thr, 8x4 micro, f32x2 FMA, reg-prefetch ----------------
__global__ __launch_bounds__(256)
void gemm_kernel(const float* __restrict__ A, int lda, long sA,
                 const float* __restrict__ B, int ldbn, int ldbk, long sB,
                 float* __restrict__ Cp, int ldc, long sC,
                 const float* __restrict__ bias, long sBias,
                 int M, int N, int K) {
    int batch = blockIdx.z;
    A  += (long)batch * sA;
    B  += (long)batch * sB;
    Cp += (long)batch * sC;
    if (bias) bias += (long)batch * sBias;

    __shared__ float As[16][132];
    __shared__ float Bs[16][68];
    int t = threadIdx.x;
    int tx = t & 15, ty = t >> 4;
    int m0 = blockIdx.y * 128, n0 = blockIdx.x * 64;

    int ar = t >> 2, ac = (t & 3) * 4;
    const bool bvec = (ldbk == 1);
    const float* Abase = A + (long)(m0 + ar) * lda + ac;

    float4 ra0, ra1, rb;
    float rbs[4];
    ra0 = *(const float4*)(Abase);
    ra1 = *(const float4*)(Abase + (long)64 * lda);
    if (bvec) {
        rb = *(const float4*)(B + (long)(n0 + ar) * ldbn + ac);
    } else {
        #pragma unroll
        for (int q = 0; q < 4; q++) {
            int idx = t + 256*q; int nn = idx & 63, kk = idx >> 6;
            rbs[q] = B[(long)(n0 + nn) + (long)kk * ldbk];
        }
    }

    u64 acc2[4][4] = {};   // [m-pair][j]
    for (int k0 = 0; k0 < K; k0 += 16) {
        As[ac+0][ar]    = ra0.x; As[ac+1][ar]    = ra0.y; As[ac+2][ar]    = ra0.z; As[ac+3][ar]    = ra0.w;
        As[ac+0][ar+64] = ra1.x; As[ac+1][ar+64] = ra1.y; As[ac+2][ar+64] = ra1.z; As[ac+3][ar+64] = ra1.w;
        if (bvec) {
            Bs[ac+0][ar] = rb.x; Bs[ac+1][ar] = rb.y; Bs[ac+2][ar] = rb.z; Bs[ac+3][ar] = rb.w;
        } else {
            #pragma unroll
            for (int q = 0; q < 4; q++) {
                int idx = t + 256*q; int nn = idx & 63, kk = idx >> 6;
                Bs[kk][nn] = rbs[q];
            }
        }
        __syncthreads();
        if (k0 + 16 < K) {
            const float* An = Abase + k0 + 16;
            ra0 = *(const float4*)(An);
            ra1 = *(const float4*)(An + (long)64 * lda);
            if (bvec) {
                rb = *(const float4*)(B + (long)(n0 + ar) * ldbn + k0 + 16 + ac);
            } else {
                #pragma unroll
                for (int q = 0; q < 4; q++) {
                    int idx = t + 256*q; int nn = idx & 63, kk = idx >> 6;
                    rbs[q] = B[(long)(n0 + nn) + (long)(k0 + 16 + kk) * ldbk];
                }
            }
        }
        #pragma unroll
        for (int k = 0; k < 16; k++) {
            ulonglong2 aA = *(const ulonglong2*)(&As[k][ty*8]);      // {m0m1, m2m3}
            ulonglong2 aB = *(const ulonglong2*)(&As[k][ty*8+4]);    // {m4m5, m6m7}
            float4 bq = *(const float4*)(&Bs[k][tx*4]);
            u64 ap0 = aA.x, ap1 = aA.y, ap2 = aB.x, ap3 = aB.y;
            u64 bs0 = splat2(bq.x), bs1 = splat2(bq.y), bs2 = splat2(bq.z), bs3 = splat2(bq.w);
            acc2[0][0]=fma2(ap0,bs0,acc2[0][0]); acc2[0][1]=fma2(ap0,bs1,acc2[0][1]);
            acc2[0][2]=fma2(ap0,bs2,acc2[0][2]); acc2[0][3]=fma2(ap0,bs3,acc2[0][3]);
            acc2[1][0]=fma2(ap1,bs0,acc2[1][0]); acc2[1][1]=fma2(ap1,bs1,acc2[1][1]);
            acc2[1][2]=fma2(ap1,bs2,acc2[1][2]); acc2[1][3]=fma2(ap1,bs3,acc2[1][3]);
            acc2[2][0]=fma2(ap2,bs0,acc2[2][0]); acc2[2][1]=fma2(ap2,bs1,acc2[2][1]);
            acc2[2][2]=fma2(ap2,bs2,acc2[2][2]); acc2[2][3]=fma2(ap2,bs3,acc2[2][3]);
            acc2[3][0]=fma2(ap3,bs0,acc2[3][0]); acc2[3][1]=fma2(ap3,bs1,acc2[3][1]);
            acc2[3][2]=fma2(ap3,bs2,acc2[3][2]); acc2[3][3]=fma2(ap3,bs3,acc2[3][3]);
        }
        __syncthreads();
    }
    float4 bb = make_float4(0.f,0.f,0.f,0.f);
    if (bias) bb = *(const float4*)(bias + n0 + tx*4);
    #pragma unroll
    for (int mp = 0; mp < 4; mp++) {
        float2 u0 = unpack2(acc2[mp][0]);
        float2 u1 = unpack2(acc2[mp][1]);
        float2 u2 = unpack2(acc2[mp][2]);
        float2 u3 = unpack2(acc2[mp][3]);
        int mA = m0 + ty*8 + mp*2, mB = mA + 1;
        float4 oA = make_float4(u0.x+bb.x, u1.x+bb.y, u2.x+bb.z, u3.x+bb.w);
        float4 oB = make_float4(u0.y+bb.x, u1.y+bb.y, u2.y+bb.z, u3.y+bb.w);
        *(float4*)(&Cp[(long)mA * ldc + n0 + tx*4]) = oA;
        *(float4*)(&Cp[(long)mB * ldc + n0 + tx*4]) = oB;
    }
}

// ---------------- 4) fused attention, f32x2, occupancy 2 ----------------
#define SKS 268
#define SQS 516
#define OFF_SQ   17152
#define OFF_RED  21280
#define OFF_SC   25376
#define OFF_SA   25888
#define OFF_SMAX 26400
#define OFF_SRS  26408
#define OFF_RXY  26416
#define OFF_W1E  26544
#define OFF_W1O  26800
#define OFF_B1S  27056
#define ATTN_FLTS 27312
#define ATTN_SMEM (ATTN_FLTS*4)

__global__ __launch_bounds__(512, 2)
void attn_kernel(const float* __restrict__ qk, const float* __restrict__ key2,
                 const float* __restrict__ r, const float* __restrict__ w1,
                 const float* __restrict__ b1, float* __restrict__ ctx) {
    extern __shared__ float smf[];
    float* skey = smf;
    float* sq   = smf + OFF_SQ;
    float* red  = smf + OFF_RED;
    float* sc   = smf + OFF_SC;
    float* sa   = smf + OFF_SA;
    float* smax = smf + OFF_SMAX;
    float* srs  = smf + OFF_SRS;
    float* rxy  = smf + OFF_RXY;
    float* w1e  = smf + OFF_W1E;
    float* w1o  = smf + OFF_W1O;
    float* b1s  = smf + OFF_B1S;

    int b = blockIdx.x, t = threadIdx.x;

    const float* keyb = key2 + (long)b * (64*256);
    #pragma unroll
    for (int q = 0; q < 8; q++) {
        int idx = t + 512*q;
        int row = idx >> 6, c4 = (idx & 63) * 4;
        *(float4*)(skey + row*SKS + c4) = *(const float4*)(keyb + row*256 + c4);
    }
    {
        const float4* qsrc = (const float4*)(qk + (long)b * 4096);
        #pragma unroll
        for (int q = 0; q < 2; q++) {
            int idx = t + 512*q;
            int row = idx >> 7, c = idx & 127;
            *(float4*)(sq + row*SQS + c*4) = qsrc[row*128 + c];
        }
    }
    if (t < 128) {
        rxy[t] = r[b*128 + t];
    } else if (t < 384) {
        int h = t - 128;
        w1e[h] = w1[2*h]; w1o[h] = w1[2*h+1]; b1s[h] = b1[h];
    }
    __syncthreads();

    // ---- phase 1: scores (256 threads, 8 j-slices, 4h x 4k micro, f32x2) ----
    if (t < 256) {
        int s = t >> 5, lane = t & 31;
        int hq = lane >> 4, kq = lane & 15;
        int h0 = hq * 4, jb = s * 32;
        u64 acc2[4][4] = {};
        // interp half
        #pragma unroll
        for (int st = 0; st < 8; st++) {
            int jj = jb + st*4;
            ulonglong2 a0 = *(const ulonglong2*)(sq + (h0+0)*SQS + jj);
            ulonglong2 a1 = *(const ulonglong2*)(sq + (h0+1)*SQS + jj);
            ulonglong2 a2 = *(const ulonglong2*)(sq + (h0+2)*SQS + jj);
            ulonglong2 a3 = *(const ulonglong2*)(sq + (h0+3)*SQS + jj);
            #pragma unroll
            for (int m = 0; m < 4; m++) {
                ulonglong2 bv = *(const ulonglong2*)(skey + (kq + 16*m)*SKS + jj);
                acc2[0][m] = fma2(a0.x, bv.x, acc2[0][m]); acc2[0][m] = fma2(a0.y, bv.y, acc2[0][m]);
                acc2[1][m] = fma2(a1.x, bv.x, acc2[1][m]); acc2[1][m] = fma2(a1.y, bv.y, acc2[1][m]);
                acc2[2][m] = fma2(a2.x, bv.x, acc2[2][m]); acc2[2][m] = fma2(a2.y, bv.y, acc2[2][m]);
                acc2[3][m] = fma2(a3.x, bv.x, acc2[3][m]); acc2[3][m] = fma2(a3.y, bv.y, acc2[3][m]);
            }
        }
        // r_proj half (generated packed)
        u64 xs[4], ys[4];
        #pragma unroll
        for (int m = 0; m < 4; m++) {
            int k = kq + 16*m;
            xs[m] = splat2(rxy[2*k]);
            ys[m] = splat2(rxy[2*k+1]);
        }
        #pragma unroll
        for (int st = 0; st < 8; st++) {
            int w = jb + st*4, jj = 256 + w;
            ulonglong2 a0 = *(const ulonglong2*)(sq + (h0+0)*SQS + jj);
            ulonglong2 a1 = *(const ulonglong2*)(sq + (h0+1)*SQS + jj);
            ulonglong2 a2 = *(const ulonglong2*)(sq + (h0+2)*SQS + jj);
            ulonglong2 a3 = *(const ulonglong2*)(sq + (h0+3)*SQS + jj);
            ulonglong2 we2 = *(const ulonglong2*)(w1e + w);
            ulonglong2 wo2 = *(const ulonglong2*)(w1o + w);
            ulonglong2 bc2 = *(const ulonglong2*)(b1s + w);
            #pragma unroll
            for (int m = 0; m < 4; m++) {
                u64 bv01 = fma2(xs[m], we2.x, fma2(ys[m], wo2.x, bc2.x));
                u64 bv23 = fma2(xs[m], we2.y, fma2(ys[m], wo2.y, bc2.y));
                acc2[0][m] = fma2(a0.x, bv01, acc2[0][m]); acc2[0][m] = fma2(a0.y, bv23, acc2[0][m]);
                acc2[1][m] = fma2(a1.x, bv01, acc2[1][m]); acc2[1][m] = fma2(a1.y, bv23, acc2[1][m]);
                acc2[2][m] = fma2(a2.x, bv01, acc2[2][m]); acc2[2][m] = fma2(a2.y, bv23, acc2[2][m]);
                acc2[3][m] = fma2(a3.x, bv01, acc2[3][m]); acc2[3][m] = fma2(a3.y, bv23, acc2[3][m]);
            }
        }
        #pragma unroll
        for (int hi = 0; hi < 4; hi++)
            #pragma unroll
            for (int m = 0; m < 4; m++) {
                float2 u = unpack2(acc2[hi][m]);
                red[s*512 + (h0+hi)*64 + m*16 + kq] = u.x + u.y;
            }
    }
    __syncthreads();
    {
        float v = 0.f;
        #pragma unroll
        for (int s2 = 0; s2 < 8; s2++) v += red[s2*512 + t];
        sc[t] = v * 0.125f;
    }
    __syncthreads();

    // ---- softmax over k per head: one warp, shuffles ----
    if (t < 32) {
        int h = t >> 2, seg = t & 3;
        const float* p = sc + h*64 + seg*16;
        float mx = p[0];
        #pragma unroll
        for (int i = 1; i < 16; i++) mx = fmaxf(mx, p[i]);
        mx = fmaxf(mx, __shfl_xor_sync(0xffffffffu, mx, 1));
        mx = fmaxf(mx, __shfl_xor_sync(0xffffffffu, mx, 2));
        float sm = 0.f;
        #pragma unroll
        for (int i = 0; i < 16; i++) sm += __expf(p[i] - mx);
        sm += __shfl_xor_sync(0xffffffffu, sm, 1);
        sm += __shfl_xor_sync(0xffffffffu, sm, 2);
        if (seg == 0) { smax[h] = mx; srs[h] = 1.0f / sm; }
    }
    __syncthreads();
    sa[t] = __expf(sc[t] - smax[t >> 6]) * srs[t >> 6];
    __syncthreads();

    // ---- phase 3: ctx = attn @ key (256 threads, 4h x 4j, f32x2) ----
    if (t < 256) {
        int hq = t >> 7, jq = t & 127;
        int h0 = hq * 4, j0 = jq * 4;
        const float* sa0 = sa + (h0+0)*64;
        const float* sa1 = sa + (h0+1)*64;
        const float* sa2 = sa + (h0+2)*64;
        const float* sa3 = sa + (h0+3)*64;
        u64 acc2[4][2] = {};
        if (j0 < 256) {
            #pragma unroll
            for (int k4 = 0; k4 < 64; k4 += 4) {
                float4 av0 = *(const float4*)(sa0 + k4);
                float4 av1 = *(const float4*)(sa1 + k4);
                float4 av2 = *(const float4*)(sa2 + k4);
                float4 av3 = *(const float4*)(sa3 + k4);
                float a0r[4] = {av0.x, av0.y, av0.z, av0.w};
                float a1r[4] = {av1.x, av1.y, av1.z, av1.w};
                float a2r[4] = {av2.x, av2.y, av2.z, av2.w};
                float a3r[4] = {av3.x, av3.y, av3.z, av3.w};
                #pragma unroll
                for (int kk = 0; kk < 4; kk++) {
                    ulonglong2 bv = *(const ulonglong2*)(skey + (k4+kk)*SKS + j0);
                    u64 s0 = splat2(a0r[kk]), s1 = splat2(a1r[kk]);
                    u64 s2 = splat2(a2r[kk]), s3 = splat2(a3r[kk]);
                    acc2[0][0]=fma2(s0,bv.x,acc2[0][0]); acc2[0][1]=fma2(s0,bv.y,acc2[0][1]);
                    acc2[1][0]=fma2(s1,bv.x,acc2[1][0]); acc2[1][1]=fma2(s1,bv.y,acc2[1][1]);
                    acc2[2][0]=fma2(s2,bv.x,acc2[2][0]); acc2[2][1]=fma2(s2,bv.y,acc2[2][1]);
                    acc2[3][0]=fma2(s3,bv.x,acc2[3][0]); acc2[3][1]=fma2(s3,bv.y,acc2[3][1]);
                }
            }
        } else {
            int w = j0 - 256;
            ulonglong2 we2 = *(const ulonglong2*)(w1e + w);
            ulonglong2 wo2 = *(const ulonglong2*)(w1o + w);
            ulonglong2 bc2 = *(const ulonglong2*)(b1s + w);
            #pragma unroll
            for (int k4 = 0; k4 < 64; k4 += 4) {
                float4 av0 = *(const float4*)(sa0 + k4);
                float4 av1 = *(const float4*)(sa1 + k4);
                float4 av2 = *(const float4*)(sa2 + k4);
                float4 av3 = *(const float4*)(sa3 + k4);
                float a0r[4] = {av0.x, av0.y, av0.z, av0.w};
                float a1r[4] = {av1.x, av1.y, av1.z, av1.w};
                float a2r[4] = {av2.x, av2.y, av2.z, av2.w};
                float a3r[4] = {av3.x, av3.y, av3.z, av3.w};
                #pragma unroll
                for (int kk = 0; kk < 4; kk++) {
                    int k = k4 + kk;
                    u64 xs = splat2(rxy[2*k]), ys = splat2(rxy[2*k+1]);
                    u64 bv01 = fma2(xs, we2.x, fma2(ys, wo2.x, bc2.x));
                    u64 bv23 = fma2(xs, we2.y, fma2(ys, wo2.y, bc2.y));
                    u64 s0 = splat2(a0r[kk]), s1 = splat2(a1r[kk]);
                    u64 s2 = splat2(a2r[kk]), s3 = splat2(a3r[kk]);
                    acc2[0][0]=fma2(s0,bv01,acc2[0][0]); acc2[0][1]=fma2(s0,bv23,acc2[0][1]);
                    acc2[1][0]=fma2(s1,bv01,acc2[1][0]); acc2[1][1]=fma2(s1,bv23,acc2[1][1]);
                    acc2[2][0]=fma2(s2,bv01,acc2[2][0]); acc2[2][1]=fma2(s2,bv23,acc2[2][1]);
                    acc2[3][0]=fma2(s3,bv01,acc2[3][0]); acc2[3][1]=fma2(s3,bv23,acc2[3][1]);
                }
            }
        }
        float* ctxb = ctx + (long)b * 4096;
        #pragma unroll
        for (int hi = 0; hi < 4; hi++) {
            float2 u0 = unpack2(acc2[hi][0]);
            float2 u1 = unpack2(acc2[hi][1]);
            float4 o = make_float4(u0.x, u0.y, u1.x, u1.y);
            *(float4*)(ctxb + (h0+hi)*512 + j0) = o;
        }
    }
}

// ---------------- host launcher ----------------
extern "C" void kernel_launch(void* const* d_in, const int* in_sizes, int n_in,
                              void* d_out, int out_size) {
    const float* Z          = (const float*)d_in[0];
    const float* Q          = (const float*)d_in[1];
    const float* q_z        = (const float*)d_in[2];
    const float* r          = (const float*)d_in[3];
    const float* w1         = (const float*)d_in[4];
    const float* b1         = (const float*)d_in[5];
    const float* w2         = (const float*)d_in[6];
    const float* b2         = (const float*)d_in[7];
    const float* in_proj_w  = (const float*)d_in[8];
    const float* in_proj_b  = (const float*)d_in[9];
    const float* out_proj_w = (const float*)d_in[10];
    const float* out_proj_b = (const float*)d_in[11];
    float* outp = (float*)d_out;

    float *pKey2, *pQuery, *pQl, *pQk, *pCtx, *pOut1;
    cudaGetSymbolAddress((void**)&pKey2,  g_key2);
    cudaGetSymbolAddress((void**)&pQuery, g_query);
    cudaGetSymbolAddress((void**)&pQl,    g_ql);
    cudaGetSymbolAddress((void**)&pQk,    g_qk);
    cudaGetSymbolAddress((void**)&pCtx,   g_ctx);
    cudaGetSymbolAddress((void**)&pOut1,  g_out1);

    cudaFuncSetAttribute(attn_kernel,
                         cudaFuncAttributeMaxDynamicSharedMemorySize, ATTN_SMEM);

    transpose_kernel<<<dim3((HWn*HWn)/32, Cn/32), dim3(32, 8)>>>(Z);

    interp_kernel<<<NPn/32, 256>>>(r);

    query_kernel<<<SQn, 512>>>(Q, q_z, w2, b2, outp);

    gemm_kernel<<<dim3(En/64, SQn/128, 1), 256>>>(
        pQuery, En, 0L,
        in_proj_w, En, 1, 0L,
        pQl, En, 0L,
        in_proj_b, 0L,
        SQn, En, En);

    gemm_kernel<<<dim3(En/64, SQn/128, NHn), 256>>>(
        pQl, En, (long)HDn,
        in_proj_w + (long)En*En, 1, En, (long)HDn*En,
        pQk, NHn*En, (long)En,
        (const float*)0, 0L,
        SQn, En, HDn);

    attn_kernel<<<SQn, 512, ATTN_SMEM>>>(pQk, pKey2, r, w1, b1, pCtx);

    gemm_kernel<<<dim3(HDn/64, SQn/128, NHn), 256>>>(
        pCtx, NHn*En, (long)En,
        in_proj_w + (long)2*En*En, En, 1, (long)HDn*En,
        pOut1, En, (long)HDn,
        in_proj_b + (long)2*En, (long)HDn,
        SQn, HDn, En);

    gemm_kernel<<<dim3(En/64, SQn/128, 1), 256>>>(
        pOut1, En, 0L,
        out_proj_w, En, 1, 0L,
        outp + 256, 768, 0L,
        out_proj_b, 0L,
        SQn, En, En);
}

// round 8
// speedup vs baseline: 2.3097x; 1.1972x over previous
#include <cuda_runtime.h>
#include <math.h>

#define SQn   2048
#define SKn   64
#define Cn    256
#define HWn   256
#define En    512
#define NPn   (SQn*SKn)
#define NHn   8
#define HDn   64

typedef unsigned long long u64;

__device__ __forceinline__ u64 fma2(u64 a, u64 b, u64 c) {
    u64 d;
    asm("fma.rn.f32x2 %0, %1, %2, %3;" : "=l"(d) : "l"(a), "l"(b), "l"(c));
    return d;
}
__device__ __forceinline__ u64 pack2(float lo, float hi) {
    u64 v;
    asm("mov.b64 %0, {%1, %2};" : "=l"(v) : "f"(lo), "f"(hi));
    return v;
}
__device__ __forceinline__ float2 unpack2(u64 v) {
    float lo, hi;
    asm("mov.b64 {%0, %1}, %2;" : "=f"(lo), "=f"(hi) : "l"(v));
    return make_float2(lo, hi);
}
__device__ __forceinline__ u64 splat2(float a) { return pack2(a, a); }

// ---------------- scratch ----------------
__device__ float g_Zt[(size_t)Cn*HWn*HWn];      // 67 MB   Zt[x][y][c]
__device__ float g_key2[(size_t)NPn*256];       // 134 MB  interp half of key
__device__ float g_ql[(size_t)SQn*En];
__device__ float g_qk[(size_t)SQn*NHn*En];
__device__ float g_ctx[(size_t)SQn*NHn*En];
__device__ float g_out1[(size_t)SQn*En];

// ---------------- 1) transpose Z (C, HW*HW) -> Zt (HW*HW, C) ----------------
__global__ void transpose_kernel(const float* __restrict__ Z) {
    __shared__ float tile[32][33];
    int xy0 = blockIdx.x * 32;
    int c0  = blockIdx.y * 32;
    int tx = threadIdx.x, ty = threadIdx.y;   // 32 x 8
    #pragma unroll
    for (int i = 0; i < 32; i += 8)
        tile[ty + i][tx] = Z[(long)(c0 + ty + i) * (HWn*HWn) + xy0 + tx];
    __syncthreads();
    #pragma unroll
    for (int i = 0; i < 32; i += 8)
        g_Zt[(long)(xy0 + ty + i) * Cn + c0 + tx] = tile[tx][ty + i];
}

// ---------------- 2) FAT kernel: gemm1(query fused) | qz->out copy | interp ----------------
// blocks [0,128): gemm1  ql = query @ Wq^T + bq     (query built on the fly)
// blocks [128,144): copy q_z into outp[:, 0:256)
// blocks [144, 4240): bilinear interp -> g_key2
#define FAT_GEMM_BLKS 128
#define FAT_COPY_BLKS 16
#define FAT_INTERP_OFF (FAT_GEMM_BLKS + FAT_COPY_BLKS)

struct InterpS { float sres[256][33]; int soff[32]; float sdx[32], sdy[32]; };
struct GemmS   { float As[16][132]; float Bs[16][68]; };

__global__ __launch_bounds__(256)
void fat_kernel(const float* __restrict__ Z_unused,
                const float* __restrict__ r,
                const float* __restrict__ q_z,
                const float* __restrict__ Q,
                const float* __restrict__ w2,
                const float* __restrict__ b2,
                const float* __restrict__ in_proj_w,
                const float* __restrict__ in_proj_b,
                float* __restrict__ outp) {
    __shared__ __align__(16) char smraw[sizeof(InterpS)];
    int bx = blockIdx.x;
    int t = threadIdx.x;

    if (bx < FAT_GEMM_BLKS) {
        // ---------- gemm1 with fused query A ----------
        GemmS* S = (GemmS*)smraw;
        int tx = t & 15, ty = t >> 4;
        int m0 = (bx >> 3) * 128;          // 16 m-tiles
        int n0 = (bx & 7) * 64;            // 8 n-tiles
        int ar = t >> 2, ac = (t & 3) * 4;

        int rowA = m0 + ar, rowB = m0 + ar + 64;
        float qa0 = Q[rowA*3+0], qa1 = Q[rowA*3+1], qa2 = Q[rowA*3+2];
        float qb0 = Q[rowB*3+0], qb1 = Q[rowB*3+1], qb2 = Q[rowB*3+2];

        const float* B = in_proj_w;

        auto loadA = [&](int row, float q0, float q1, float q2, int k)->float4 {
            if (k < 256) {
                return *(const float4*)(q_z + (long)row*256 + k);
            } else {
                int h = k - 256;
                const float* w2r = w2 + h*3;
                float4 v;
                v.x = q0*w2r[0] + q1*w2r[1]  + q2*w2r[2]  + b2[h+0];
                v.y = q0*w2r[3] + q1*w2r[4]  + q2*w2r[5]  + b2[h+1];
                v.z = q0*w2r[6] + q1*w2r[7]  + q2*w2r[8]  + b2[h+2];
                v.w = q0*w2r[9] + q1*w2r[10] + q2*w2r[11] + b2[h+3];
                return v;
            }
        };

        float4 ra0 = loadA(rowA, qa0, qa1, qa2, ac);
        float4 ra1 = loadA(rowB, qb0, qb1, qb2, ac);
        float4 rb  = *(const float4*)(B + (long)(n0 + ar) * En + ac);

        u64 acc2[4][4] = {};
        for (int k0 = 0; k0 < En; k0 += 16) {
            S->As[ac+0][ar]    = ra0.x; S->As[ac+1][ar]    = ra0.y; S->As[ac+2][ar]    = ra0.z; S->As[ac+3][ar]    = ra0.w;
            S->As[ac+0][ar+64] = ra1.x; S->As[ac+1][ar+64] = ra1.y; S->As[ac+2][ar+64] = ra1.z; S->As[ac+3][ar+64] = ra1.w;
            S->Bs[ac+0][ar] = rb.x; S->Bs[ac+1][ar] = rb.y; S->Bs[ac+2][ar] = rb.z; S->Bs[ac+3][ar] = rb.w;
            __syncthreads();
            if (k0 + 16 < En) {
                ra0 = loadA(rowA, qa0, qa1, qa2, k0 + 16 + ac);
                ra1 = loadA(rowB, qb0, qb1, qb2, k0 + 16 + ac);
                rb  = *(const float4*)(B + (long)(n0 + ar) * En + k0 + 16 + ac);
            }
            #pragma unroll
            for (int k = 0; k < 16; k++) {
                ulonglong2 aA = *(const ulonglong2*)(&S->As[k][ty*8]);
                ulonglong2 aB = *(const ulonglong2*)(&S->As[k][ty*8+4]);
                float4 bq = *(const float4*)(&S->Bs[k][tx*4]);
                u64 ap0 = aA.x, ap1 = aA.y, ap2 = aB.x, ap3 = aB.y;
                u64 bs0 = splat2(bq.x), bs1 = splat2(bq.y), bs2 = splat2(bq.z), bs3 = splat2(bq.w);
                acc2[0][0]=fma2(ap0,bs0,acc2[0][0]); acc2[0][1]=fma2(ap0,bs1,acc2[0][1]);
                acc2[0][2]=fma2(ap0,bs2,acc2[0][2]); acc2[0][3]=fma2(ap0,bs3,acc2[0][3]);
                acc2[1][0]=fma2(ap1,bs0,acc2[1][0]); acc2[1][1]=fma2(ap1,bs1,acc2[1][1]);
                acc2[1][2]=fma2(ap1,bs2,acc2[1][2]); acc2[1][3]=fma2(ap1,bs3,acc2[1][3]);
                acc2[2][0]=fma2(ap2,bs0,acc2[2][0]); acc2[2][1]=fma2(ap2,bs1,acc2[2][1]);
                acc2[2][2]=fma2(ap2,bs2,acc2[2][2]); acc2[2][3]=fma2(ap2,bs3,acc2[2][3]);
                acc2[3][0]=fma2(ap3,bs0,acc2[3][0]); acc2[3][1]=fma2(ap3,bs1,acc2[3][1]);
                acc2[3][2]=fma2(ap3,bs2,acc2[3][2]); acc2[3][3]=fma2(ap3,bs3,acc2[3][3]);
            }
            __syncthreads();
        }
        float4 bb = *(const float4*)(in_proj_b + n0 + tx*4);
        #pragma unroll
        for (int mp = 0; mp < 4; mp++) {
            float2 u0 = unpack2(acc2[mp][0]);
            float2 u1 = unpack2(acc2[mp][1]);
            float2 u2 = unpack2(acc2[mp][2]);
            float2 u3 = unpack2(acc2[mp][3]);
            int mA = m0 + ty*8 + mp*2, mB = mA + 1;
            float4 oA = make_float4(u0.x+bb.x, u1.x+bb.y, u2.x+bb.z, u3.x+bb.w);
            float4 oB = make_float4(u0.y+bb.x, u1.y+bb.y, u2.y+bb.z, u3.y+bb.w);
            *(float4*)(&g_ql[(long)mA * En + n0 + tx*4]) = oA;
            *(float4*)(&g_ql[(long)mB * En + n0 + tx*4]) = oB;
        }
    } else if (bx < FAT_INTERP_OFF) {
        // ---------- q_z -> outp[:, 0:256) ----------
        int r0 = (bx - FAT_GEMM_BLKS) * 128;   // 128 rows per block
        #pragma unroll
        for (int i = 0; i < 32; i++) {
            int idx = i * 256 + t;             // 8192 float4 per block
            int row = r0 + (idx >> 6);
            int c4  = (idx & 63) * 4;
            float4 v = *(const float4*)(q_z + (long)row*256 + c4);
            *(float4*)(outp + (long)row*768 + c4) = v;
        }
    } else {
        // ---------- bilinear interp ----------
        InterpS* S = (InterpS*)smraw;
        int p0 = (bx - FAT_INTERP_OFF) * 32;
        if (t < 32) {
            float x = r[2*(p0+t)], y = r[2*(p0+t)+1];
            int x1 = (int)x, y1 = (int)y;
            S->soff[t] = (x1*HWn + y1)*Cn;
            S->sdx[t] = x - (float)x1;
            S->sdy[t] = y - (float)y1;
        }
        __syncthreads();
        int wp = t >> 5, l = t & 31;
        #pragma unroll
        for (int pi = 0; pi < 4; pi++) {
            int pl = wp*4 + pi;
            long off = S->soff[pl];
            float dx = S->sdx[pl], dy = S->sdy[pl];
            float omdx = 1.0f - dx, omdy = 1.0f - dy;
            #pragma unroll
            for (int rep = 0; rep < 2; rep++) {
                int c = rep*128 + l*4;
                const float* z11 = g_Zt + off + c;
                float4 a  = *(const float4*)(z11);
                float4 cq = *(const float4*)(z11 + Cn);
                float4 b  = *(const float4*)(z11 + HWn*Cn);
                float4 d  = *(const float4*)(z11 + HWn*Cn + Cn);
                S->sres[c+0][pl] = (a.x*omdx + b.x*dx)*omdy + (cq.x*omdx + d.x*dx)*dy;
                S->sres[c+1][pl] = (a.y*omdx + b.y*dx)*omdy + (cq.y*omdx + d.y*dx)*dy;
                S->sres[c+2][pl] = (a.z*omdx + b.z*dx)*omdy + (cq.z*omdx + d.z*dx)*dy;
                S->sres[c+3][pl] = (a.w*omdx + b.w*dx)*omdy + (cq.w*omdx + d.w*dx)*dy;
            }
        }
        __syncthreads();
        long rowhi = (long)(p0 >> 8);
        int  colb  = p0 & 255;
        #pragma unroll
        for (int i = 0; i < 32; i++) {
            int c = wp*32 + i;
            g_key2[((long)c*512 + rowhi)*256 + colb + l] = S->sres[c][l];
        }
    }
}

// ---------------- generic GEMM: 128x64 tile, 256 thr, 8x4 micro, f32x2 ----------------
__global__ __launch_bounds__(256)
void gemm_kernel(const float* __restrict__ A, int lda, long sA,
                 const float* __restrict__ B, int ldbn, int ldbk, long sB,
                 float* __restrict__ Cp, int ldc, long sC,
                 const float* __restrict__ bias, long sBias,
                 int M, int N, int K) {
    int batch = blockIdx.z;
    A  += (long)batch * sA;
    B  += (long)batch * sB;
    Cp += (long)batch * sC;
    if (bias) bias += (long)batch * sBias;

    __shared__ float As[16][132];
    __shared__ float Bs[16][68];
    int t = threadIdx.x;
    int tx = t & 15, ty = t >> 4;
    int m0 = blockIdx.y * 128, n0 = blockIdx.x * 64;

    int ar = t >> 2, ac = (t & 3) * 4;
    const bool bvec = (ldbk == 1);
    const float* Abase = A + (long)(m0 + ar) * lda + ac;

    float4 ra0, ra1, rb;
    float rbs[4];
    ra0 = *(const float4*)(Abase);
    ra1 = *(const float4*)(Abase + (long)64 * lda);
    if (bvec) {
        rb = *(const float4*)(B + (long)(n0 + ar) * ldbn + ac);
    } else {
        #pragma unroll
        for (int q = 0; q < 4; q++) {
            int idx = t + 256*q; int nn = idx & 63, kk = idx >> 6;
            rbs[q] = B[(long)(n0 + nn) + (long)kk * ldbk];
        }
    }

    u64 acc2[4][4] = {};
    for (int k0 = 0; k0 < K; k0 += 16) {
        As[ac+0][ar]    = ra0.x; As[ac+1][ar]    = ra0.y; As[ac+2][ar]    = ra0.z; As[ac+3][ar]    = ra0.w;
        As[ac+0][ar+64] = ra1.x; As[ac+1][ar+64] = ra1.y; As[ac+2][ar+64] = ra1.z; As[ac+3][ar+64] = ra1.w;
        if (bvec) {
            Bs[ac+0][ar] = rb.x; Bs[ac+1][ar] = rb.y; Bs[ac+2][ar] = rb.z; Bs[ac+3][ar] = rb.w;
        } else {
            #pragma unroll
            for (int q = 0; q < 4; q++) {
                int idx = t + 256*q; int nn = idx & 63, kk = idx >> 6;
                Bs[kk][nn] = rbs[q];
            }
        }
        __syncthreads();
        if (k0 + 16 < K) {
            const float* An = Abase + k0 + 16;
            ra0 = *(const float4*)(An);
            ra1 = *(const float4*)(An + (long)64 * lda);
            if (bvec) {
                rb = *(const float4*)(B + (long)(n0 + ar) * ldbn + k0 + 16 + ac);
            } else {
                #pragma unroll
                for (int q = 0; q < 4; q++) {
                    int idx = t + 256*q; int nn = idx & 63, kk = idx >> 6;
                    rbs[q] = B[(long)(n0 + nn) + (long)(k0 + 16 + kk) * ldbk];
                }
            }
        }
        #pragma unroll
        for (int k = 0; k < 16; k++) {
            ulonglong2 aA = *(const ulonglong2*)(&As[k][ty*8]);
            ulonglong2 aB = *(const ulonglong2*)(&As[k][ty*8+4]);
            float4 bq = *(const float4*)(&Bs[k][tx*4]);
            u64 ap0 = aA.x, ap1 = aA.y, ap2 = aB.x, ap3 = aB.y;
            u64 bs0 = splat2(bq.x), bs1 = splat2(bq.y), bs2 = splat2(bq.z), bs3 = splat2(bq.w);
            acc2[0][0]=fma2(ap0,bs0,acc2[0][0]); acc2[0][1]=fma2(ap0,bs1,acc2[0][1]);
            acc2[0][2]=fma2(ap0,bs2,acc2[0][2]); acc2[0][3]=fma2(ap0,bs3,acc2[0][3]);
            acc2[1][0]=fma2(ap1,bs0,acc2[1][0]); acc2[1][1]=fma2(ap1,bs1,acc2[1][1]);
            acc2[1][2]=fma2(ap1,bs2,acc2[1][2]); acc2[1][3]=fma2(ap1,bs3,acc2[1][3]);
            acc2[2][0]=fma2(ap2,bs0,acc2[2][0]); acc2[2][1]=fma2(ap2,bs1,acc2[2][1]);
            acc2[2][2]=fma2(ap2,bs2,acc2[2][2]); acc2[2][3]=fma2(ap2,bs3,acc2[2][3]);
            acc2[3][0]=fma2(ap3,bs0,acc2[3][0]); acc2[3][1]=fma2(ap3,bs1,acc2[3][1]);
            acc2[3][2]=fma2(ap3,bs2,acc2[3][2]); acc2[3][3]=fma2(ap3,bs3,acc2[3][3]);
        }
        __syncthreads();
    }
    float4 bb = make_float4(0.f,0.f,0.f,0.f);
    if (bias) bb = *(const float4*)(bias + n0 + tx*4);
    #pragma unroll
    for (int mp = 0; mp < 4; mp++) {
        float2 u0 = unpack2(acc2[mp][0]);
        float2 u1 = unpack2(acc2[mp][1]);
        float2 u2 = unpack2(acc2[mp][2]);
        float2 u3 = unpack2(acc2[mp][3]);
        int mA = m0 + ty*8 + mp*2, mB = mA + 1;
        float4 oA = make_float4(u0.x+bb.x, u1.x+bb.y, u2.x+bb.z, u3.x+bb.w);
        float4 oB = make_float4(u0.y+bb.x, u1.y+bb.y, u2.y+bb.z, u3.y+bb.w);
        *(float4*)(&Cp[(long)mA * ldc + n0 + tx*4]) = oA;
        *(float4*)(&Cp[(long)mB * ldc + n0 + tx*4]) = oB;
    }
}

// ---------------- 4) fused attention, 256 threads (no spills), occupancy 2 ----------------
#define SKS 268
#define SQS 516
#define OFF_SQ   17152
#define OFF_RED  21280
#define OFF_SC   25376
#define OFF_SA   25888
#define OFF_SMAX 26400
#define OFF_SRS  26408
#define OFF_RXY  26416
#define OFF_W1E  26544
#define OFF_W1O  26800
#define OFF_B1S  27056
#define ATTN_FLTS 27312
#define ATTN_SMEM (ATTN_FLTS*4)

__global__ __launch_bounds__(256, 2)
void attn_kernel(const float* __restrict__ qk, const float* __restrict__ key2,
                 const float* __restrict__ r, const float* __restrict__ w1,
                 const float* __restrict__ b1, float* __restrict__ ctx) {
    extern __shared__ float smf[];
    float* skey = smf;
    float* sq   = smf + OFF_SQ;
    float* red  = smf + OFF_RED;
    float* sc   = smf + OFF_SC;
    float* sa   = smf + OFF_SA;
    float* smax = smf + OFF_SMAX;
    float* srs  = smf + OFF_SRS;
    float* rxy  = smf + OFF_RXY;
    float* w1e  = smf + OFF_W1E;
    float* w1o  = smf + OFF_W1O;
    float* b1s  = smf + OFF_B1S;

    int b = blockIdx.x, t = threadIdx.x;

    const float* keyb = key2 + (long)b * (64*256);
    #pragma unroll
    for (int q = 0; q < 16; q++) {
        int idx = t + 256*q;
        int row = idx >> 6, c4 = (idx & 63) * 4;
        *(float4*)(skey + row*SKS + c4) = *(const float4*)(keyb + row*256 + c4);
    }
    {
        const float4* qsrc = (const float4*)(qk + (long)b * 4096);
        #pragma unroll
        for (int q = 0; q < 4; q++) {
            int idx = t + 256*q;
            int row = idx >> 7, c = idx & 127;
            *(float4*)(sq + row*SQS + c*4) = qsrc[row*128 + c];
        }
    }
    if (t < 128) rxy[t] = r[b*128 + t];
    w1e[t] = w1[2*t]; w1o[t] = w1[2*t+1]; b1s[t] = b1[t];
    __syncthreads();

    // ---- phase 1: scores (256 threads, 8 j-slices, 4h x 4k micro, f32x2) ----
    {
        int s = t >> 5, lane = t & 31;
        int hq = lane >> 4, kq = lane & 15;
        int h0 = hq * 4, jb = s * 32;
        u64 acc2[4][4] = {};
        // interp half
        #pragma unroll
        for (int st = 0; st < 8; st++) {
            int jj = jb + st*4;
            ulonglong2 a0 = *(const ulonglong2*)(sq + (h0+0)*SQS + jj);
            ulonglong2 a1 = *(const ulonglong2*)(sq + (h0+1)*SQS + jj);
            ulonglong2 a2 = *(const ulonglong2*)(sq + (h0+2)*SQS + jj);
            ulonglong2 a3 = *(const ulonglong2*)(sq + (h0+3)*SQS + jj);
            #pragma unroll
            for (int m = 0; m < 4; m++) {
                ulonglong2 bv = *(const ulonglong2*)(skey + (kq + 16*m)*SKS + jj);
                acc2[0][m] = fma2(a0.x, bv.x, acc2[0][m]); acc2[0][m] = fma2(a0.y, bv.y, acc2[0][m]);
                acc2[1][m] = fma2(a1.x, bv.x, acc2[1][m]); acc2[1][m] = fma2(a1.y, bv.y, acc2[1][m]);
                acc2[2][m] = fma2(a2.x, bv.x, acc2[2][m]); acc2[2][m] = fma2(a2.y, bv.y, acc2[2][m]);
                acc2[3][m] = fma2(a3.x, bv.x, acc2[3][m]); acc2[3][m] = fma2(a3.y, bv.y, acc2[3][m]);
            }
        }
        // r_proj half (generated packed)
        u64 xs[4], ys[4];
        #pragma unroll
        for (int m = 0; m < 4; m++) {
            int k = kq + 16*m;
            xs[m] = splat2(rxy[2*k]);
            ys[m] = splat2(rxy[2*k+1]);
        }
        #pragma unroll
        for (int st = 0; st < 8; st++) {
            int w = jb + st*4, jj = 256 + w;
            ulonglong2 a0 = *(const ulonglong2*)(sq + (h0+0)*SQS + jj);
            ulonglong2 a1 = *(const ulonglong2*)(sq + (h0+1)*SQS + jj);
            ulonglong2 a2 = *(const ulonglong2*)(sq + (h0+2)*SQS + jj);
            ulonglong2 a3 = *(const ulonglong2*)(sq + (h0+3)*SQS + jj);
            ulonglong2 we2 = *(const ulonglong2*)(w1e + w);
            ulonglong2 wo2 = *(const ulonglong2*)(w1o + w);
            ulonglong2 bc2 = *(const ulonglong2*)(b1s + w);
            #pragma unroll
            for (int m = 0; m < 4; m++) {
                u64 bv01 = fma2(xs[m], we2.x, fma2(ys[m], wo2.x, bc2.x));
                u64 bv23 = fma2(xs[m], we2.y, fma2(ys[m], wo2.y, bc2.y));
                acc2[0][m] = fma2(a0.x, bv01, acc2[0][m]); acc2[0][m] = fma2(a0.y, bv23, acc2[0][m]);
                acc2[1][m] = fma2(a1.x, bv01, acc2[1][m]); acc2[1][m] = fma2(a1.y, bv23, acc2[1][m]);
                acc2[2][m] = fma2(a2.x, bv01, acc2[2][m]); acc2[2][m] = fma2(a2.y, bv23, acc2[2][m]);
                acc2[3][m] = fma2(a3.x, bv01, acc2[3][m]); acc2[3][m] = fma2(a3.y, bv23, acc2[3][m]);
            }
        }
        #pragma unroll
        for (int hi = 0; hi < 4; hi++)
            #pragma unroll
            for (int m = 0; m < 4; m++) {
                float2 u = unpack2(acc2[hi][m]);
                red[s*512 + (h0+hi)*64 + m*16 + kq] = u.x + u.y;
            }
    }
    __syncthreads();
    #pragma unroll
    for (int e0 = 0; e0 < 2; e0++) {
        int e = t + e0*256;
        float v = 0.f;
        #pragma unroll
        for (int s2 = 0; s2 < 8; s2++) v += red[s2*512 + e];
        sc[e] = v * 0.125f;
    }
    __syncthreads();

    // ---- softmax over k per head: one warp, shuffles ----
    if (t < 32) {
        int h = t >> 2, seg = t & 3;
        const float* p = sc + h*64 + seg*16;
        float mx = p[0];
        #pragma unroll
        for (int i = 1; i < 16; i++) mx = fmaxf(mx, p[i]);
        mx = fmaxf(mx, __shfl_xor_sync(0xffffffffu, mx, 1));
        mx = fmaxf(mx, __shfl_xor_sync(0xffffffffu, mx, 2));
        float sm = 0.f;
        #pragma unroll
        for (int i = 0; i < 16; i++) sm += __expf(p[i] - mx);
        sm += __shfl_xor_sync(0xffffffffu, sm, 1);
        sm += __shfl_xor_sync(0xffffffffu, sm, 2);
        if (seg == 0) { smax[h] = mx; srs[h] = 1.0f / sm; }
    }
    __syncthreads();
    sa[t]     = __expf(sc[t]     - smax[t >> 6])        * srs[t >> 6];
    sa[t+256] = __expf(sc[t+256] - smax[(t+256) >> 6])  * srs[(t+256) >> 6];
    __syncthreads();

    // ---- phase 3: ctx = attn @ key (256 threads, 4h x 4j, f32x2) ----
    {
        int hq = t >> 7, jq = t & 127;
        int h0 = hq * 4, j0 = jq * 4;
        const float* sa0 = sa + (h0+0)*64;
        const float* sa1 = sa + (h0+1)*64;
        const float* sa2 = sa + (h0+2)*64;
        const float* sa3 = sa + (h0+3)*64;
        u64 acc2[4][2] = {};
        if (j0 < 256) {
            #pragma unroll
            for (int k4 = 0; k4 < 64; k4 += 4) {
                float4 av0 = *(const float4*)(sa0 + k4);
                float4 av1 = *(const float4*)(sa1 + k4);
                float4 av2 = *(const float4*)(sa2 + k4);
                float4 av3 = *(const float4*)(sa3 + k4);
                float a0r[4] = {av0.x, av0.y, av0.z, av0.w};
                float a1r[4] = {av1.x, av1.y, av1.z, av1.w};
                float a2r[4] = {av2.x, av2.y, av2.z, av2.w};
                float a3r[4] = {av3.x, av3.y, av3.z, av3.w};
                #pragma unroll
                for (int kk = 0; kk < 4; kk++) {
                    ulonglong2 bv = *(const ulonglong2*)(skey + (k4+kk)*SKS + j0);
                    u64 s0 = splat2(a0r[kk]), s1 = splat2(a1r[kk]);
                    u64 s2 = splat2(a2r[kk]), s3 = splat2(a3r[kk]);
                    acc2[0][0]=fma2(s0,bv.x,acc2[0][0]); acc2[0][1]=fma2(s0,bv.y,acc2[0][1]);
                    acc2[1][0]=fma2(s1,bv.x,acc2[1][0]); acc2[1][1]=fma2(s1,bv.y,acc2[1][1]);
                    acc2[2][0]=fma2(s2,bv.x,acc2[2][0]); acc2[2][1]=fma2(s2,bv.y,acc2[2][1]);
                    acc2[3][0]=fma2(s3,bv.x,acc2[3][0]); acc2[3][1]=fma2(s3,bv.y,acc2[3][1]);
                }
            }
        } else {
            int w = j0 - 256;
            ulonglong2 we2 = *(const ulonglong2*)(w1e + w);
            ulonglong2 wo2 = *(const ulonglong2*)(w1o + w);
            ulonglong2 bc2 = *(const ulonglong2*)(b1s + w);
            #pragma unroll
            for (int k4 = 0; k4 < 64; k4 += 4) {
                float4 av0 = *(const float4*)(sa0 + k4);
                float4 av1 = *(const float4*)(sa1 + k4);
                float4 av2 = *(const float4*)(sa2 + k4);
                float4 av3 = *(const float4*)(sa3 + k4);
                float a0r[4] = {av0.x, av0.y, av0.z, av0.w};
                float a1r[4] = {av1.x, av1.y, av1.z, av1.w};
                float a2r[4] = {av2.x, av2.y, av2.z, av2.w};
                float a3r[4] = {av3.x, av3.y, av3.z, av3.w};
                #pragma unroll
                for (int kk = 0; kk < 4; kk++) {
                    int k = k4 + kk;
                    u64 xs = splat2(rxy[2*k]), ys = splat2(rxy[2*k+1]);
                    u64 bv01 = fma2(xs, we2.x, fma2(ys, wo2.x, bc2.x));
                    u64 bv23 = fma2(xs, we2.y, fma2(ys, wo2.y, bc2.y));
                    u64 s0 = splat2(a0r[kk]), s1 = splat2(a1r[kk]);
                    u64 s2 = splat2(a2r[kk]), s3 = splat2(a3r[kk]);
                    acc2[0][0]=fma2(s0,bv01,acc2[0][0]); acc2[0][1]=fma2(s0,bv23,acc2[0][1]);
                    acc2[1][0]=fma2(s1,bv01,acc2[1][0]); acc2[1][1]=fma2(s1,bv23,acc2[1][1]);
                    acc2[2][0]=fma2(s2,bv01,acc2[2][0]); acc2[2][1]=fma2(s2,bv23,acc2[2][1]);
                    acc2[3][0]=fma2(s3,bv01,acc2[3][0]); acc2[3][1]=fma2(s3,bv23,acc2[3][1]);
                }
            }
        }
        float* ctxb = ctx + (long)b * 4096;
        #pragma unroll
        for (int hi = 0; hi < 4; hi++) {
            float2 u0 = unpack2(acc2[hi][0]);
            float2 u1 = unpack2(acc2[hi][1]);
            float4 o = make_float4(u0.x, u0.y, u1.x, u1.y);
            *(float4*)(ctxb + (h0+hi)*512 + j0) = o;
        }
    }
}

// ---------------- host launcher ----------------
extern "C" void kernel_launch(void* const* d_in, const int* in_sizes, int n_in,
                              void* d_out, int out_size) {
    const float* Z          = (const float*)d_in[0];
    const float* Q          = (const float*)d_in[1];
    const float* q_z        = (const float*)d_in[2];
    const float* r          = (const float*)d_in[3];
    const float* w1         = (const float*)d_in[4];
    const float* b1         = (const float*)d_in[5];
    const float* w2         = (const float*)d_in[6];
    const float* b2         = (const float*)d_in[7];
    const float* in_proj_w  = (const float*)d_in[8];
    const float* in_proj_b  = (const float*)d_in[9];
    const float* out_proj_w = (const float*)d_in[10];
    const float* out_proj_b = (const float*)d_in[11];
    float* outp = (float*)d_out;

    float *pKey2, *pQl, *pQk, *pCtx, *pOut1;
    cudaGetSymbolAddress((void**)&pKey2,  g_key2);
    cudaGetSymbolAddress((void**)&pQl,    g_ql);
    cudaGetSymbolAddress((void**)&pQk,    g_qk);
    cudaGetSymbolAddress((void**)&pCtx,   g_ctx);
    cudaGetSymbolAddress((void**)&pOut1,  g_out1);

    cudaFuncSetAttribute(attn_kernel,
                         cudaFuncAttributeMaxDynamicSharedMemorySize, ATTN_SMEM);

    // 1) transpose Z -> Zt
    transpose_kernel<<<dim3((HWn*HWn)/32, Cn/32), dim3(32, 8)>>>(Z);

    // 2) fat kernel: gemm1(fused query) + qz->out copy + interp (overlapped)
    fat_kernel<<<FAT_INTERP_OFF + NPn/32, 256>>>(
        Z, r, q_z, Q, w2, b2, in_proj_w, in_proj_b, outp);

    // 3) qk[b][h][n] = sum_d ql[b][h*64+d] * Wk[h*64+d][n]
    gemm_kernel<<<dim3(En/64, SQn/128, NHn), 256>>>(
        pQl, En, (long)HDn,
        in_proj_w + (long)En*En, 1, En, (long)HDn*En,
        pQk, NHn*En, (long)En,
        (const float*)0, 0L,
        SQn, En, HDn);

    // 4) fused attention
    attn_kernel<<<SQn, 256, ATTN_SMEM>>>(pQk, pKey2, r, w1, b1, pCtx);

    // 5) out1[b][h*64+d] = ctx[b][h][:] . Wv[h*64+d][:] + bv
    gemm_kernel<<<dim3(HDn/64, SQn/128, NHn), 256>>>(
        pCtx, NHn*En, (long)En,
        in_proj_w + (long)2*En*En, En, 1, (long)HDn*En,
        pOut1, En, (long)HDn,
        in_proj_b + (long)2*En, (long)HDn,
        SQn, HDn, En);

    // 6) final out_proj into d_out cols [256,768)
    gemm_kernel<<<dim3(En/64, SQn/128, 1), 256>>>(
        pOut1, En, 0L,
        out_proj_w, En, 1, 0L,
        outp + 256, 768, 0L,
        out_proj_b, 0L,
        SQn, En, En);
}

// round 9
// speedup vs baseline: 2.3230x; 1.0058x over previous
#include <cuda_runtime.h>
#include <math.h>
#include <stdint.h>

#define SQn   2048
#define SKn   64
#define Cn    256
#define HWn   256
#define En    512
#define NPn   (SQn*SKn)
#define NHn   8
#define HDn   64

typedef unsigned long long u64;

__device__ __forceinline__ u64 fma2(u64 a, u64 b, u64 c) {
    u64 d;
    asm("fma.rn.f32x2 %0, %1, %2, %3;" : "=l"(d) : "l"(a), "l"(b), "l"(c));
    return d;
}
__device__ __forceinline__ u64 pack2(float lo, float hi) {
    u64 v;
    asm("mov.b64 %0, {%1, %2};" : "=l"(v) : "f"(lo), "f"(hi));
    return v;
}
__device__ __forceinline__ float2 unpack2(u64 v) {
    float lo, hi;
    asm("mov.b64 {%0, %1}, %2;" : "=f"(lo), "=f"(hi) : "l"(v));
    return make_float2(lo, hi);
}
__device__ __forceinline__ u64 splat2(float a) { return pack2(a, a); }

__device__ __forceinline__ uint32_t f2tf(float f) {
    uint32_t u;
    asm("cvt.rna.tf32.f32 %0, %1;" : "=r"(u) : "f"(f));
    return u;
}
__device__ __forceinline__ uint4 cvt4(float4 v) {
    return make_uint4(f2tf(v.x), f2tf(v.y), f2tf(v.z), f2tf(v.w));
}
__device__ __forceinline__ void mma_tf32(float& d0, float& d1, float& d2, float& d3,
                                         uint32_t a0, uint32_t a1, uint32_t a2, uint32_t a3,
                                         uint32_t b0, uint32_t b1) {
    asm volatile(
        "mma.sync.aligned.m16n8k8.row.col.f32.tf32.tf32.f32 "
        "{%0,%1,%2,%3}, {%4,%5,%6,%7}, {%8,%9}, {%0,%1,%2,%3};"
        : "+f"(d0), "+f"(d1), "+f"(d2), "+f"(d3)
        : "r"(a0), "r"(a1), "r"(a2), "r"(a3), "r"(b0), "r"(b1));
}

// ---------------- scratch ----------------
__device__ float g_Zt[(size_t)Cn*HWn*HWn];      // 67 MB   Zt[x][y][c]
__device__ float g_key2[(size_t)NPn*256];       // 134 MB  interp half of key
__device__ float g_ql[(size_t)SQn*En];
__device__ float g_qk[(size_t)SQn*NHn*En];
__device__ float g_ctx[(size_t)SQn*NHn*En];
__device__ float g_out1[(size_t)SQn*En];

// ---------------- 1) transpose Z (C, HW*HW) -> Zt (HW*HW, C) ----------------
__global__ void transpose_kernel(const float* __restrict__ Z) {
    __shared__ float tile[32][33];
    int xy0 = blockIdx.x * 32;
    int c0  = blockIdx.y * 32;
    int tx = threadIdx.x, ty = threadIdx.y;   // 32 x 8
    #pragma unroll
    for (int i = 0; i < 32; i += 8)
        tile[ty + i][tx] = Z[(long)(c0 + ty + i) * (HWn*HWn) + xy0 + tx];
    __syncthreads();
    #pragma unroll
    for (int i = 0; i < 32; i += 8)
        g_Zt[(long)(xy0 + ty + i) * Cn + c0 + tx] = tile[tx][ty + i];
}

// ================= tf32 mma compute core (shared logic, macro-free duplication) =================
// smem: As[128][20] m-major tf32 bits, Bs[64][20] n-major tf32 bits. 256 thr = 8 warps.
// warp w: wm = w&3 (m-offset wm*32), wn = w>>2 (n-offset wn*32). lane: g = l>>2, q = l&3.
// Per 16-k chunk: 2 k8 steps; per step: A frags (2 msub), B frags (4 nsub), 8 mma.

#define GEMM_AS_SZ (128*20)
#define GEMM_BS_SZ (64*20)

// ---------------- 2) FAT kernel: gemm1(query fused, tf32) | qz->out copy | interp ----------------
#define FAT_GEMM_BLKS 128
#define FAT_COPY_BLKS 16
#define FAT_INTERP_OFF (FAT_GEMM_BLKS + FAT_COPY_BLKS)

struct InterpS { float sres[256][33]; int soff[32]; float sdx[32], sdy[32]; };
struct GemmS   { uint32_t As[GEMM_AS_SZ]; uint32_t Bs[GEMM_BS_SZ]; };

__global__ __launch_bounds__(256)
void fat_kernel(const float* __restrict__ r,
                const float* __restrict__ q_z,
                const float* __restrict__ Q,
                const float* __restrict__ w2,
                const float* __restrict__ b2,
                const float* __restrict__ in_proj_w,
                const float* __restrict__ in_proj_b,
                float* __restrict__ outp) {
    __shared__ __align__(16) char smraw[sizeof(InterpS)];
    int bx = blockIdx.x;
    int t = threadIdx.x;

    if (bx < FAT_GEMM_BLKS) {
        // ---------- gemm1 (tf32) with fused query A ----------
        GemmS* S = (GemmS*)smraw;
        int m0 = (bx >> 3) * 128;
        int n0 = (bx & 7) * 64;
        int ar = t >> 2, ac = (t & 3) * 4;
        int w = t >> 5, l = t & 31;
        int wm = w & 3, wn = w >> 2;
        int g = l >> 2, q = l & 3;

        int rowA = m0 + ar, rowB = m0 + ar + 64;
        float qa0 = Q[rowA*3+0], qa1 = Q[rowA*3+1], qa2 = Q[rowA*3+2];
        float qb0 = Q[rowB*3+0], qb1 = Q[rowB*3+1], qb2 = Q[rowB*3+2];

        auto loadA = [&](int row, float q0, float q1, float q2, int k)->float4 {
            if (k < 256) {
                return *(const float4*)(q_z + (long)row*256 + k);
            } else {
                int h = k - 256;
                const float* w2r = w2 + h*3;
                float4 v;
                v.x = q0*w2r[0] + q1*w2r[1]  + q2*w2r[2]  + b2[h+0];
                v.y = q0*w2r[3] + q1*w2r[4]  + q2*w2r[5]  + b2[h+1];
                v.z = q0*w2r[6] + q1*w2r[7]  + q2*w2r[8]  + b2[h+2];
                v.w = q0*w2r[9] + q1*w2r[10] + q2*w2r[11] + b2[h+3];
                return v;
            }
        };

        uint4 ua0 = cvt4(loadA(rowA, qa0, qa1, qa2, ac));
        uint4 ua1 = cvt4(loadA(rowB, qb0, qb1, qb2, ac));
        uint4 ub  = cvt4(*(const float4*)(in_proj_w + (long)(n0 + ar) * En + ac));

        float acc[2][4][4] = {};
        for (int k0 = 0; k0 < En; k0 += 16) {
            *(uint4*)(&S->As[(ar     )*20 + ac]) = ua0;
            *(uint4*)(&S->As[(ar + 64)*20 + ac]) = ua1;
            *(uint4*)(&S->Bs[(ar     )*20 + ac]) = ub;
            __syncthreads();
            if (k0 + 16 < En) {
                ua0 = cvt4(loadA(rowA, qa0, qa1, qa2, k0 + 16 + ac));
                ua1 = cvt4(loadA(rowB, qb0, qb1, qb2, k0 + 16 + ac));
                ub  = cvt4(*(const float4*)(in_proj_w + (long)(n0 + ar) * En + k0 + 16 + ac));
            }
            #pragma unroll
            for (int ks = 0; ks < 2; ks++) {
                int kk = ks * 8;
                uint32_t af[2][4];
                #pragma unroll
                for (int ms = 0; ms < 2; ms++) {
                    int mr = wm*32 + ms*16 + g;
                    af[ms][0] = S->As[(mr    )*20 + kk + q];
                    af[ms][1] = S->As[(mr + 8)*20 + kk + q];
                    af[ms][2] = S->As[(mr    )*20 + kk + q + 4];
                    af[ms][3] = S->As[(mr + 8)*20 + kk + q + 4];
                }
                uint32_t bf[4][2];
                #pragma unroll
                for (int ns = 0; ns < 4; ns++) {
                    int nc = wn*32 + ns*8 + g;
                    bf[ns][0] = S->Bs[nc*20 + kk + q];
                    bf[ns][1] = S->Bs[nc*20 + kk + q + 4];
                }
                #pragma unroll
                for (int ms = 0; ms < 2; ms++)
                    #pragma unroll
                    for (int ns = 0; ns < 4; ns++)
                        mma_tf32(acc[ms][ns][0], acc[ms][ns][1], acc[ms][ns][2], acc[ms][ns][3],
                                 af[ms][0], af[ms][1], af[ms][2], af[ms][3],
                                 bf[ns][0], bf[ns][1]);
            }
            __syncthreads();
        }
        #pragma unroll
        for (int ms = 0; ms < 2; ms++)
            #pragma unroll
            for (int ns = 0; ns < 4; ns++) {
                int row0 = m0 + wm*32 + ms*16 + g;
                int col  = n0 + wn*32 + ns*8 + 2*q;
                float bx0 = in_proj_b[col], bx1 = in_proj_b[col+1];
                *(float2*)(&g_ql[(long)row0*En + col]) =
                    make_float2(acc[ms][ns][0] + bx0, acc[ms][ns][1] + bx1);
                *(float2*)(&g_ql[(long)(row0+8)*En + col]) =
                    make_float2(acc[ms][ns][2] + bx0, acc[ms][ns][3] + bx1);
            }
    } else if (bx < FAT_INTERP_OFF) {
        // ---------- q_z -> outp[:, 0:256) ----------
        int r0 = (bx - FAT_GEMM_BLKS) * 128;
        #pragma unroll
        for (int i = 0; i < 32; i++) {
            int idx = i * 256 + t;
            int row = r0 + (idx >> 6);
            int c4  = (idx & 63) * 4;
            float4 v = *(const float4*)(q_z + (long)row*256 + c4);
            *(float4*)(outp + (long)row*768 + c4) = v;
        }
    } else {
        // ---------- bilinear interp ----------
        InterpS* S = (InterpS*)smraw;
        int p0 = (bx - FAT_INTERP_OFF) * 32;
        if (t < 32) {
            float x = r[2*(p0+t)], y = r[2*(p0+t)+1];
            int x1 = (int)x, y1 = (int)y;
            S->soff[t] = (x1*HWn + y1)*Cn;
            S->sdx[t] = x - (float)x1;
            S->sdy[t] = y - (float)y1;
        }
        __syncthreads();
        int wp = t >> 5, l = t & 31;
        #pragma unroll
        for (int pi = 0; pi < 4; pi++) {
            int pl = wp*4 + pi;
            long off = S->soff[pl];
            float dx = S->sdx[pl], dy = S->sdy[pl];
            float omdx = 1.0f - dx, omdy = 1.0f - dy;
            #pragma unroll
            for (int rep = 0; rep < 2; rep++) {
                int c = rep*128 + l*4;
                const float* z11 = g_Zt + off + c;
                float4 a  = *(const float4*)(z11);
                float4 cq = *(const float4*)(z11 + Cn);
                float4 b  = *(const float4*)(z11 + HWn*Cn);
                float4 d  = *(const float4*)(z11 + HWn*Cn + Cn);
                S->sres[c+0][pl] = (a.x*omdx + b.x*dx)*omdy + (cq.x*omdx + d.x*dx)*dy;
                S->sres[c+1][pl] = (a.y*omdx + b.y*dx)*omdy + (cq.y*omdx + d.y*dx)*dy;
                S->sres[c+2][pl] = (a.z*omdx + b.z*dx)*omdy + (cq.z*omdx + d.z*dx)*dy;
                S->sres[c+3][pl] = (a.w*omdx + b.w*dx)*omdy + (cq.w*omdx + d.w*dx)*dy;
            }
        }
        __syncthreads();
        long rowhi = (long)(p0 >> 8);
        int  colb  = p0 & 255;
        #pragma unroll
        for (int i = 0; i < 32; i++) {
            int c = wp*32 + i;
            g_key2[((long)c*512 + rowhi)*256 + colb + l] = S->sres[c][l];
        }
    }
}

// ---------------- generic tf32 GEMM: 128x64 tile, 256 thr ----------------
// C[m][n] = sum_k A[m*lda+k] * B[n*ldbn + k*ldbk] + bias[n]
__global__ __launch_bounds__(256)
void gemm_kernel(const float* __restrict__ A, int lda, long sA,
                 const float* __restrict__ B, int ldbn, int ldbk, long sB,
                 float* __restrict__ Cp, int ldc, long sC,
                 const float* __restrict__ bias, long sBias,
                 int M, int N, int K) {
    int batch = blockIdx.z;
    A  += (long)batch * sA;
    B  += (long)batch * sB;
    Cp += (long)batch * sC;
    if (bias) bias += (long)batch * sBias;

    __shared__ uint32_t As[GEMM_AS_SZ];
    __shared__ uint32_t Bs[GEMM_BS_SZ];
    int t = threadIdx.x;
    int m0 = blockIdx.y * 128, n0 = blockIdx.x * 64;
    int ar = t >> 2, ac = (t & 3) * 4;
    int w = t >> 5, l = t & 31;
    int wm = w & 3, wn = w >> 2;
    int g = l >> 2, q = l & 3;

    const bool bvec = (ldbk == 1);
    const float* Abase = A + (long)(m0 + ar) * lda + ac;

    uint4 ua0 = cvt4(*(const float4*)(Abase));
    uint4 ua1 = cvt4(*(const float4*)(Abase + (long)64 * lda));
    uint4 ub;
    uint32_t ubs[4];
    if (bvec) {
        ub = cvt4(*(const float4*)(B + (long)(n0 + ar) * ldbn + ac));
    } else {
        #pragma unroll
        for (int p = 0; p < 4; p++) {
            int idx = t + 256*p; int nn = idx & 63, kk = idx >> 6;
            ubs[p] = f2tf(B[(long)(n0 + nn) + (long)kk * ldbk]);
        }
    }

    float acc[2][4][4] = {};
    for (int k0 = 0; k0 < K; k0 += 16) {
        *(uint4*)(&As[(ar     )*20 + ac]) = ua0;
        *(uint4*)(&As[(ar + 64)*20 + ac]) = ua1;
        if (bvec) {
            *(uint4*)(&Bs[ar*20 + ac]) = ub;
        } else {
            #pragma unroll
            for (int p = 0; p < 4; p++) {
                int idx = t + 256*p; int nn = idx & 63, kk = idx >> 6;
                Bs[nn*20 + kk] = ubs[p];
            }
        }
        __syncthreads();
        if (k0 + 16 < K) {
            const float* An = Abase + k0 + 16;
            ua0 = cvt4(*(const float4*)(An));
            ua1 = cvt4(*(const float4*)(An + (long)64 * lda));
            if (bvec) {
                ub = cvt4(*(const float4*)(B + (long)(n0 + ar) * ldbn + k0 + 16 + ac));
            } else {
                #pragma unroll
                for (int p = 0; p < 4; p++) {
                    int idx = t + 256*p; int nn = idx & 63, kk = idx >> 6;
                    ubs[p] = f2tf(B[(long)(n0 + nn) + (long)(k0 + 16 + kk) * ldbk]);
                }
            }
        }
        #pragma unroll
        for (int ks = 0; ks < 2; ks++) {
            int kk = ks * 8;
            uint32_t af[2][4];
            #pragma unroll
            for (int ms = 0; ms < 2; ms++) {
                int mr = wm*32 + ms*16 + g;
                af[ms][0] = As[(mr    )*20 + kk + q];
                af[ms][1] = As[(mr + 8)*20 + kk + q];
                af[ms][2] = As[(mr    )*20 + kk + q + 4];
                af[ms][3] = As[(mr + 8)*20 + kk + q + 4];
            }
            uint32_t bf[4][2];
            #pragma unroll
            for (int ns = 0; ns < 4; ns++) {
                int nc = wn*32 + ns*8 + g;
                bf[ns][0] = Bs[nc*20 + kk + q];
                bf[ns][1] = Bs[nc*20 + kk + q + 4];
            }
            #pragma unroll
            for (int ms = 0; ms < 2; ms++)
                #pragma unroll
                for (int ns = 0; ns < 4; ns++)
                    mma_tf32(acc[ms][ns][0], acc[ms][ns][1], acc[ms][ns][2], acc[ms][ns][3],
                             af[ms][0], af[ms][1], af[ms][2], af[ms][3],
                             bf[ns][0], bf[ns][1]);
        }
        __syncthreads();
    }
    #pragma unroll
    for (int ms = 0; ms < 2; ms++)
        #pragma unroll
        for (int ns = 0; ns < 4; ns++) {
            int row0 = m0 + wm*32 + ms*16 + g;
            int col  = n0 + wn*32 + ns*8 + 2*q;
            float bx0 = 0.f, bx1 = 0.f;
            if (bias) { bx0 = bias[col]; bx1 = bias[col+1]; }
            *(float2*)(&Cp[(long)row0*ldc + col]) =
                make_float2(acc[ms][ns][0] + bx0, acc[ms][ns][1] + bx1);
            *(float2*)(&Cp[(long)(row0+8)*ldc + col]) =
                make_float2(acc[ms][ns][2] + bx0, acc[ms][ns][3] + bx1);
        }
}

// ---------------- 4) fused attention, 256 threads, occupancy 2 (unchanged) ----------------
#define SKS 268
#define SQS 516
#define OFF_SQ   17152
#define OFF_RED  21280
#define OFF_SC   25376
#define OFF_SA   25888
#define OFF_SMAX 26400
#define OFF_SRS  26408
#define OFF_RXY  26416
#define OFF_W1E  26544
#define OFF_W1O  26800
#define OFF_B1S  27056
#define ATTN_FLTS 27312
#define ATTN_SMEM (ATTN_FLTS*4)

__global__ __launch_bounds__(256, 2)
void attn_kernel(const float* __restrict__ qk, const float* __restrict__ key2,
                 const float* __restrict__ r, const float* __restrict__ w1,
                 const float* __restrict__ b1, float* __restrict__ ctx) {
    extern __shared__ float smf[];
    float* skey = smf;
    float* sq   = smf + OFF_SQ;
    float* red  = smf + OFF_RED;
    float* sc   = smf + OFF_SC;
    float* sa   = smf + OFF_SA;
    float* smax = smf + OFF_SMAX;
    float* srs  = smf + OFF_SRS;
    float* rxy  = smf + OFF_RXY;
    float* w1e  = smf + OFF_W1E;
    float* w1o  = smf + OFF_W1O;
    float* b1s  = smf + OFF_B1S;

    int b = blockIdx.x, t = threadIdx.x;

    const float* keyb = key2 + (long)b * (64*256);
    #pragma unroll
    for (int q = 0; q < 16; q++) {
        int idx = t + 256*q;
        int row = idx >> 6, c4 = (idx & 63) * 4;
        *(float4*)(skey + row*SKS + c4) = *(const float4*)(keyb + row*256 + c4);
    }
    {
        const float4* qsrc = (const float4*)(qk + (long)b * 4096);
        #pragma unroll
        for (int q = 0; q < 4; q++) {
            int idx = t + 256*q;
            int row = idx >> 7, c = idx & 127;
            *(float4*)(sq + row*SQS + c*4) = qsrc[row*128 + c];
        }
    }
    if (t < 128) rxy[t] = r[b*128 + t];
    w1e[t] = w1[2*t]; w1o[t] = w1[2*t+1]; b1s[t] = b1[t];
    __syncthreads();

    // ---- phase 1: scores ----
    {
        int s = t >> 5, lane = t & 31;
        int hq = lane >> 4, kq = lane & 15;
        int h0 = hq * 4, jb = s * 32;
        u64 acc2[4][4] = {};
        #pragma unroll
        for (int st = 0; st < 8; st++) {
            int jj = jb + st*4;
            ulonglong2 a0 = *(const ulonglong2*)(sq + (h0+0)*SQS + jj);
            ulonglong2 a1 = *(const ulonglong2*)(sq + (h0+1)*SQS + jj);
            ulonglong2 a2 = *(const ulonglong2*)(sq + (h0+2)*SQS + jj);
            ulonglong2 a3 = *(const ulonglong2*)(sq + (h0+3)*SQS + jj);
            #pragma unroll
            for (int m = 0; m < 4; m++) {
                ulonglong2 bv = *(const ulonglong2*)(skey + (kq + 16*m)*SKS + jj);
                acc2[0][m] = fma2(a0.x, bv.x, acc2[0][m]); acc2[0][m] = fma2(a0.y, bv.y, acc2[0][m]);
                acc2[1][m] = fma2(a1.x, bv.x, acc2[1][m]); acc2[1][m] = fma2(a1.y, bv.y, acc2[1][m]);
                acc2[2][m] = fma2(a2.x, bv.x, acc2[2][m]); acc2[2][m] = fma2(a2.y, bv.y, acc2[2][m]);
                acc2[3][m] = fma2(a3.x, bv.x, acc2[3][m]); acc2[3][m] = fma2(a3.y, bv.y, acc2[3][m]);
            }
        }
        u64 xs[4], ys[4];
        #pragma unroll
        for (int m = 0; m < 4; m++) {
            int k = kq + 16*m;
            xs[m] = splat2(rxy[2*k]);
            ys[m] = splat2(rxy[2*k+1]);
        }
        #pragma unroll
        for (int st = 0; st < 8; st++) {
            int w = jb + st*4, jj = 256 + w;
            ulonglong2 a0 = *(const ulonglong2*)(sq + (h0+0)*SQS + jj);
            ulonglong2 a1 = *(const ulonglong2*)(sq + (h0+1)*SQS + jj);
            ulonglong2 a2 = *(const ulonglong2*)(sq + (h0+2)*SQS + jj);
            ulonglong2 a3 = *(const ulonglong2*)(sq + (h0+3)*SQS + jj);
            ulonglong2 we2 = *(const ulonglong2*)(w1e + w);
            ulonglong2 wo2 = *(const ulonglong2*)(w1o + w);
            ulonglong2 bc2 = *(const ulonglong2*)(b1s + w);
            #pragma unroll
            for (int m = 0; m < 4; m++) {
                u64 bv01 = fma2(xs[m], we2.x, fma2(ys[m], wo2.x, bc2.x));
                u64 bv23 = fma2(xs[m], we2.y, fma2(ys[m], wo2.y, bc2.y));
                acc2[0][m] = fma2(a0.x, bv01, acc2[0][m]); acc2[0][m] = fma2(a0.y, bv23, acc2[0][m]);
                acc2[1][m] = fma2(a1.x, bv01, acc2[1][m]); acc2[1][m] = fma2(a1.y, bv23, acc2[1][m]);
                acc2[2][m] = fma2(a2.x, bv01, acc2[2][m]); acc2[2][m] = fma2(a2.y, bv23, acc2[2][m]);
                acc2[3][m] = fma2(a3.x, bv01, acc2[3][m]); acc2[3][m] = fma2(a3.y, bv23, acc2[3][m]);
            }
        }
        #pragma unroll
        for (int hi = 0; hi < 4; hi++)
            #pragma unroll
            for (int m = 0; m < 4; m++) {
                float2 u = unpack2(acc2[hi][m]);
                red[s*512 + (h0+hi)*64 + m*16 + kq] = u.x + u.y;
            }
    }
    __syncthreads();
    #pragma unroll
    for (int e0 = 0; e0 < 2; e0++) {
        int e = t + e0*256;
        float v = 0.f;
        #pragma unroll
        for (int s2 = 0; s2 < 8; s2++) v += red[s2*512 + e];
        sc[e] = v * 0.125f;
    }
    __syncthreads();

    if (t < 32) {
        int h = t >> 2, seg = t & 3;
        const float* p = sc + h*64 + seg*16;
        float mx = p[0];
        #pragma unroll
        for (int i = 1; i < 16; i++) mx = fmaxf(mx, p[i]);
        mx = fmaxf(mx, __shfl_xor_sync(0xffffffffu, mx, 1));
        mx = fmaxf(mx, __shfl_xor_sync(0xffffffffu, mx, 2));
        float sm = 0.f;
        #pragma unroll
        for (int i = 0; i < 16; i++) sm += __expf(p[i] - mx);
        sm += __shfl_xor_sync(0xffffffffu, sm, 1);
        sm += __shfl_xor_sync(0xffffffffu, sm, 2);
        if (seg == 0) { smax[h] = mx; srs[h] = 1.0f / sm; }
    }
    __syncthreads();
    sa[t]     = __expf(sc[t]     - smax[t >> 6])        * srs[t >> 6];
    sa[t+256] = __expf(sc[t+256] - smax[(t+256) >> 6])  * srs[(t+256) >> 6];
    __syncthreads();

    {
        int hq = t >> 7, jq = t & 127;
        int h0 = hq * 4, j0 = jq * 4;
        const float* sa0 = sa + (h0+0)*64;
        const float* sa1 = sa + (h0+1)*64;
        const float* sa2 = sa + (h0+2)*64;
        const float* sa3 = sa + (h0+3)*64;
        u64 acc2[4][2] = {};
        if (j0 < 256) {
            #pragma unroll
            for (int k4 = 0; k4 < 64; k4 += 4) {
                float4 av0 = *(const float4*)(sa0 + k4);
                float4 av1 = *(const float4*)(sa1 + k4);
                float4 av2 = *(const float4*)(sa2 + k4);
                float4 av3 = *(const float4*)(sa3 + k4);
                float a0r[4] = {av0.x, av0.y, av0.z, av0.w};
                float a1r[4] = {av1.x, av1.y, av1.z, av1.w};
                float a2r[4] = {av2.x, av2.y, av2.z, av2.w};
                float a3r[4] = {av3.x, av3.y, av3.z, av3.w};
                #pragma unroll
                for (int kk = 0; kk < 4; kk++) {
                    ulonglong2 bv = *(const ulonglong2*)(skey + (k4+kk)*SKS + j0);
                    u64 s0 = splat2(a0r[kk]), s1 = splat2(a1r[kk]);
                    u64 s2 = splat2(a2r[kk]), s3 = splat2(a3r[kk]);
                    acc2[0][0]=fma2(s0,bv.x,acc2[0][0]); acc2[0][1]=fma2(s0,bv.y,acc2[0][1]);
                    acc2[1][0]=fma2(s1,bv.x,acc2[1][0]); acc2[1][1]=fma2(s1,bv.y,acc2[1][1]);
                    acc2[2][0]=fma2(s2,bv.x,acc2[2][0]); acc2[2][1]=fma2(s2,bv.y,acc2[2][1]);
                    acc2[3][0]=fma2(s3,bv.x,acc2[3][0]); acc2[3][1]=fma2(s3,bv.y,acc2[3][1]);
                }
            }
        } else {
            int w = j0 - 256;
            ulonglong2 we2 = *(const ulonglong2*)(w1e + w);
            ulonglong2 wo2 = *(const ulonglong2*)(w1o + w);
            ulonglong2 bc2 = *(const ulonglong2*)(b1s + w);
            #pragma unroll
            for (int k4 = 0; k4 < 64; k4 += 4) {
                float4 av0 = *(const float4*)(sa0 + k4);
                float4 av1 = *(const float4*)(sa1 + k4);
                float4 av2 = *(const float4*)(sa2 + k4);
                float4 av3 = *(const float4*)(sa3 + k4);
                float a0r[4] = {av0.x, av0.y, av0.z, av0.w};
                float a1r[4] = {av1.x, av1.y, av1.z, av1.w};
                float a2r[4] = {av2.x, av2.y, av2.z, av2.w};
                float a3r[4] = {av3.x, av3.y, av3.z, av3.w};
                #pragma unroll
                for (int kk = 0; kk < 4; kk++) {
                    int k = k4 + kk;
                    u64 xs = splat2(rxy[2*k]), ys = splat2(rxy[2*k+1]);
                    u64 bv01 = fma2(xs, we2.x, fma2(ys, wo2.x, bc2.x));
                    u64 bv23 = fma2(xs, we2.y, fma2(ys, wo2.y, bc2.y));
                    u64 s0 = splat2(a0r[kk]), s1 = splat2(a1r[kk]);
                    u64 s2 = splat2(a2r[kk]), s3 = splat2(a3r[kk]);
                    acc2[0][0]=fma2(s0,bv01,acc2[0][0]); acc2[0][1]=fma2(s0,bv23,acc2[0][1]);
                    acc2[1][0]=fma2(s1,bv01,acc2[1][0]); acc2[1][1]=fma2(s1,bv23,acc2[1][1]);
                    acc2[2][0]=fma2(s2,bv01,acc2[2][0]); acc2[2][1]=fma2(s2,bv23,acc2[2][1]);
                    acc2[3][0]=fma2(s3,bv01,acc2[3][0]); acc2[3][1]=fma2(s3,bv23,acc2[3][1]);
                }
            }
        }
        float* ctxb = ctx + (long)b * 4096;
        #pragma unroll
        for (int hi = 0; hi < 4; hi++) {
            float2 u0 = unpack2(acc2[hi][0]);
            float2 u1 = unpack2(acc2[hi][1]);
            float4 o = make_float4(u0.x, u0.y, u1.x, u1.y);
            *(float4*)(ctxb + (h0+hi)*512 + j0) = o;
        }
    }
}

// ---------------- host launcher ----------------
extern "C" void kernel_launch(void* const* d_in, const int* in_sizes, int n_in,
                              void* d_out, int out_size) {
    const float* Z          = (const float*)d_in[0];
    const float* Q          = (const float*)d_in[1];
    const float* q_z        = (const float*)d_in[2];
    const float* r          = (const float*)d_in[3];
    const float* w1         = (const float*)d_in[4];
    const float* b1         = (const float*)d_in[5];
    const float* w2         = (const float*)d_in[6];
    const float* b2         = (const float*)d_in[7];
    const float* in_proj_w  = (const float*)d_in[8];
    const float* in_proj_b  = (const float*)d_in[9];
    const float* out_proj_w = (const float*)d_in[10];
    const float* out_proj_b = (const float*)d_in[11];
    float* outp = (float*)d_out;

    float *pKey2, *pQl, *pQk, *pCtx, *pOut1;
    cudaGetSymbolAddress((void**)&pKey2,  g_key2);
    cudaGetSymbolAddress((void**)&pQl,    g_ql);
    cudaGetSymbolAddress((void**)&pQk,    g_qk);
    cudaGetSymbolAddress((void**)&pCtx,   g_ctx);
    cudaGetSymbolAddress((void**)&pOut1,  g_out1);

    cudaFuncSetAttribute(attn_kernel,
                         cudaFuncAttributeMaxDynamicSharedMemorySize, ATTN_SMEM);

    // 1) transpose Z -> Zt
    transpose_kernel<<<dim3((HWn*HWn)/32, Cn/32), dim3(32, 8)>>>(Z);

    // 2) fat kernel: gemm1(fused query, tf32) + qz->out copy + interp
    fat_kernel<<<FAT_INTERP_OFF + NPn/32, 256>>>(
        r, q_z, Q, w2, b2, in_proj_w, in_proj_b, outp);

    // 3) qk[b][h][n] = sum_d ql[b][h*64+d] * Wk[h*64+d][n]
    gemm_kernel<<<dim3(En/64, SQn/128, NHn), 256>>>(
        pQl, En, (long)HDn,
        in_proj_w + (long)En*En, 1, En, (long)HDn*En,
        pQk, NHn*En, (long)En,
        (const float*)0, 0L,
        SQn, En, HDn);

    // 4) fused attention
    attn_kernel<<<SQn, 256, ATTN_SMEM>>>(pQk, pKey2, r, w1, b1, pCtx);

    // 5) out1[b][h*64+d] = ctx[b][h][:] . Wv[h*64+d][:] + bv
    gemm_kernel<<<dim3(HDn/64, SQn/128, NHn), 256>>>(
        pCtx, NHn*En, (long)En,
        in_proj_w + (long)2*En*En, En, 1, (long)HDn*En,
        pOut1, En, (long)HDn,
        in_proj_b + (long)2*En, (long)HDn,
        SQn, HDn, En);

    // 6) final out_proj into d_out cols [256,768)
    gemm_kernel<<<dim3(En/64, SQn/128, 1), 256>>>(
        pOut1, En, 0L,
        out_proj_w, En, 1, 0L,
        outp + 256, 768, 0L,
        out_proj_b, 0L,
        SQn, En, En);
}